// round 6
// baseline (speedup 1.0000x reference)
#include <cuda_runtime.h>
#include <math.h>
#include <stdint.h>

#define BATCH 2
#define SEQ 2048
#define DIM 2048
#define NH 16
#define NKV 4
#define HD 128
#define QKV_DIM 3072      /* (16 + 2*4) * 128 */
#define TOK (BATCH*SEQ)   /* 4096 */

// Scratch (device globals; no runtime allocation)
__device__ float g_xn[(size_t)TOK * DIM];
__device__ float g_qkv[(size_t)TOK * QKV_DIM];
__device__ float g_attn[(size_t)TOK * DIM];

__device__ __forceinline__ uint32_t f2tf(float f) {
    uint32_t u;
    asm("cvt.rna.tf32.f32 %0, %1;" : "=r"(u) : "f"(f));
    return u;
}

__device__ __forceinline__ void mma_tf32(float* c, const uint32_t* a, const uint32_t* b) {
    asm volatile(
        "mma.sync.aligned.m16n8k8.row.col.f32.tf32.tf32.f32 "
        "{%0,%1,%2,%3}, {%4,%5,%6,%7}, {%8,%9}, {%0,%1,%2,%3};"
        : "+f"(c[0]), "+f"(c[1]), "+f"(c[2]), "+f"(c[3])
        : "r"(a[0]), "r"(a[1]), "r"(a[2]), "r"(a[3]), "r"(b[0]), "r"(b[1]));
}

// ---------------------------------------------------------------------------
// RMSNorm
// ---------------------------------------------------------------------------
__global__ __launch_bounds__(256) void rmsnorm_kernel(const float* __restrict__ x,
                                                      const float* __restrict__ w,
                                                      float* __restrict__ out) {
    int row = blockIdx.x;
    int t = threadIdx.x;
    const float4* xr = (const float4*)(x + (size_t)row * DIM);
    float4 v[2];
    float s = 0.f;
#pragma unroll
    for (int i = 0; i < 2; i++) {
        v[i] = xr[t + i * 256];
        s += v[i].x * v[i].x + v[i].y * v[i].y + v[i].z * v[i].z + v[i].w * v[i].w;
    }
    __shared__ float red[8];
#pragma unroll
    for (int o = 16; o > 0; o >>= 1) s += __shfl_xor_sync(~0u, s, o);
    if ((t & 31) == 0) red[t >> 5] = s;
    __syncthreads();
    if (t < 32) {
        float ss = (t < 8) ? red[t] : 0.f;
#pragma unroll
        for (int o = 4; o > 0; o >>= 1) ss += __shfl_xor_sync(~0u, ss, o);
        if (t == 0) red[0] = rsqrtf(ss / (float)DIM + 1e-6f);
    }
    __syncthreads();
    float rs = red[0];
    float4* o4 = (float4*)(out + (size_t)row * DIM);
    const float4* w4 = (const float4*)w;
#pragma unroll
    for (int i = 0; i < 2; i++) {
        float4 wv = w4[t + i * 256];
        float4 r;
        r.x = v[i].x * rs * wv.x;
        r.y = v[i].y * rs * wv.y;
        r.z = v[i].z * rs * wv.z;
        r.w = v[i].w * rs * wv.w;
        o4[t + i * 256] = r;
    }
}

// ---------------------------------------------------------------------------
// TF32 tensor-core NT GEMM (verified R2): C[m][n] = sum_k A[m][k]*B[n][k]
// ---------------------------------------------------------------------------
#define TBM 128
#define TBN 128
#define TBK 32
#define GEMM_SMEM (2 * (TBM*TBK + TBN*TBK) * 4)  /* 64KB */

__global__ __launch_bounds__(256) void gemm_nt_tf32(const float* __restrict__ A,
                                                    const float* __restrict__ B,
                                                    float* __restrict__ C,
                                                    int M, int N, int K) {
    extern __shared__ uint32_t sm[];
    uint32_t* As = sm;
    uint32_t* Bs = sm + 2 * TBM * TBK;

    int t = threadIdx.x;
    int lane = t & 31, w = t >> 5;
    int wr = w & 3, wc = w >> 2;
    int m0 = blockIdx.y * TBM, n0 = blockIdx.x * TBN;

    float acc[2][8][4];
#pragma unroll
    for (int i = 0; i < 2; i++)
#pragma unroll
        for (int j = 0; j < 8; j++)
#pragma unroll
            for (int e = 0; e < 4; e++) acc[i][j][e] = 0.f;

    float4 Ar[4], Br[4];

#define LOAD_TILES(k0)                                                          \
    _Pragma("unroll")                                                           \
    for (int i = 0; i < 4; i++) {                                               \
        int id = t + i * 256;                                                   \
        int r = id >> 3, q = id & 7;                                            \
        Ar[i] = *(const float4*)(A + (size_t)(m0 + r) * K + (k0) + 4 * q);      \
        Br[i] = *(const float4*)(B + (size_t)(n0 + r) * K + (k0) + 4 * q);      \
    }

#define STORE_TILES(buf)                                                        \
    _Pragma("unroll")                                                           \
    for (int i = 0; i < 4; i++) {                                               \
        int id = t + i * 256;                                                   \
        int r = id >> 3, q = id & 7;                                            \
        int r16 = r & 15;                                                       \
        int fa = (r >> 4) * 4 + (q >> 1);                                       \
        int ja = (r16 >> 3) + 2 * (q & 1);                                      \
        uint32_t* ab = &As[(buf) * (TBM * TBK) + fa * 128 + (r16 & 7) * 16 + ja]; \
        ab[0]  = f2tf(Ar[i].x);                                                 \
        ab[4]  = f2tf(Ar[i].y);                                                 \
        ab[8]  = f2tf(Ar[i].z);                                                 \
        ab[12] = f2tf(Ar[i].w);                                                 \
        int n8 = r & 7;                                                         \
        int fb = (r >> 3) * 4 + (q >> 1);                                       \
        uint32_t* bb = &Bs[(buf) * (TBN * TBK) + fb * 64 + n8 * 8 + (q & 1)];   \
        bb[0] = f2tf(Br[i].x);                                                  \
        bb[2] = f2tf(Br[i].y);                                                  \
        bb[4] = f2tf(Br[i].z);                                                  \
        bb[6] = f2tf(Br[i].w);                                                  \
    }

    LOAD_TILES(0);
    STORE_TILES(0);
    __syncthreads();

    int buf = 0;
    for (int k0 = 0; k0 < K; k0 += TBK) {
        bool has_next = (k0 + TBK) < K;
        if (has_next) { LOAD_TILES(k0 + TBK); }

#pragma unroll
        for (int kt = 0; kt < 4; kt++) {
            uint32_t af[2][4], bf[8][2];
#pragma unroll
            for (int i = 0; i < 2; i++) {
                int mt = wr * 2 + i;
                const uint4 v = *(const uint4*)&As[buf * (TBM * TBK) + (mt * 4 + kt) * 128 + lane * 4];
                af[i][0] = v.x; af[i][1] = v.y; af[i][2] = v.z; af[i][3] = v.w;
            }
#pragma unroll
            for (int j = 0; j < 8; j++) {
                int nt = wc * 8 + j;
                const uint2 v = *(const uint2*)&Bs[buf * (TBN * TBK) + (nt * 4 + kt) * 64 + lane * 2];
                bf[j][0] = v.x; bf[j][1] = v.y;
            }
#pragma unroll
            for (int i = 0; i < 2; i++)
#pragma unroll
                for (int j = 0; j < 8; j++)
                    mma_tf32(acc[i][j], af[i], bf[j]);
        }

        if (has_next) { STORE_TILES(buf ^ 1); }
        __syncthreads();
        buf ^= 1;
    }

#pragma unroll
    for (int i = 0; i < 2; i++) {
#pragma unroll
        for (int j = 0; j < 8; j++) {
            int row = m0 + (wr * 2 + i) * 16 + (lane >> 2);
            int col = n0 + (wc * 8 + j) * 8 + 2 * (lane & 3);
            *(float2*)&C[(size_t)row * N + col] = make_float2(acc[i][j][0], acc[i][j][1]);
            *(float2*)&C[(size_t)(row + 8) * N + col] = make_float2(acc[i][j][2], acc[i][j][3]);
        }
    }
}

// ---------------------------------------------------------------------------
// RoPE in-place on q and k portions of qkv.
// ---------------------------------------------------------------------------
__global__ __launch_bounds__(256) void rope_kernel(float* __restrict__ qkv,
                                                   const float* __restrict__ freqs) {
    int tok = blockIdx.x;
    int s = tok % SEQ;
    for (int idx = threadIdx.x; idx < (NH + NKV) * (HD / 2); idx += blockDim.x) {
        int head = idx >> 6;
        int p = idx & 63;
        float* ptr;
        if (head < NH)
            ptr = qkv + (size_t)tok * QKV_DIM + head * HD;
        else
            ptr = qkv + (size_t)tok * QKV_DIM + NH * HD + (head - NH) * HD;
        float c  = freqs[(s * 64 + p) * 2 + 0];
        float sn = freqs[(s * 64 + p) * 2 + 1];
        float xr = ptr[2 * p];
        float xi = ptr[2 * p + 1];
        ptr[2 * p]     = xr * c - xi * sn;
        ptr[2 * p + 1] = xr * sn + xi * c;
    }
}

// ---------------------------------------------------------------------------
// Tensor-core flash attention v3 (causal, GQA), tf32 mma.sync.
// - Q fragments live in registers (read once via verified smem staging).
// - KV double-buffered: Q's staging region is reused as the 2nd buffer.
// - K gmem loads issued before S-MMAs, V before PV-MMAs (latency hidden).
// - ONE __syncthreads per KV tile.
// - launch_bounds(256,1): no register spills (smem forces 1 CTA/SM anyway).
// ---------------------------------------------------------------------------
#define FQT 128
#define FKT 64
#define PSTR 72
// u32 layout: KVbuf0 @0 (Ks0 8192 | Vs0 @8192, 8192), KVbuf1 @16384, Ps @32768
#define PS_OFF 32768
#define FLASH_SMEM ((32768 + 128*PSTR) * 4)   /* 167936 B */

__global__ __launch_bounds__(256, 1) void flash_tc(const float* __restrict__ qkv,
                                                   float* __restrict__ attn) {
    extern __shared__ uint32_t sm[];
    uint32_t* Ps = sm + PS_OFF;

    int bqt = gridDim.x - 1 - blockIdx.x;   // heavy tiles first
    int h = blockIdx.y, b = blockIdx.z;
    int kvh = h >> 2;                       // NH/NKV = 4
    int t = threadIdx.x, lane = t & 31, w = t >> 5;
    int q0 = bqt * FQT;

    const float* qbase = qkv + (size_t)b * SEQ * QKV_DIM + h * HD;
    const float* kbase = qkv + (size_t)b * SEQ * QKV_DIM + NH * HD + kvh * HD;
    const float* vbase = kbase + NKV * HD;

    // ---- Stage Q tile (128x128) into A-frag order in sm[0..16383], tf32 ----
#pragma unroll
    for (int i = 0; i < 16; i++) {
        int id = t + i * 256;
        int r = id >> 5, q = id & 31;
        float4 v = *(const float4*)(qbase + (size_t)(q0 + r) * QKV_DIM + 4 * q);
        int r16 = r & 15;
        uint32_t* p = &sm[((r >> 4) * 16 + (q >> 1)) * 128 + (r16 & 7) * 16 + (r16 >> 3) + 2 * (q & 1)];
        p[0]  = f2tf(v.x);
        p[4]  = f2tf(v.y);
        p[8]  = f2tf(v.z);
        p[12] = f2tf(v.w);
    }
    __syncthreads();

    // ---- Q fragments -> registers (64 regs), then free the staging region ----
    uint32_t qa[16][4];
#pragma unroll
    for (int kc = 0; kc < 16; kc++)
        *(uint4*)qa[kc] = *(const uint4*)&sm[(w * 16 + kc) * 128 + lane * 4];
    __syncthreads();

    // ---- Stage KV tile 0 into buffer 0 ----
#pragma unroll
    for (int i = 0; i < 8; i++) {
        int id = t + i * 256;
        int r = id >> 5, q = id & 31;
        float4 kk = *(const float4*)(kbase + (size_t)r * QKV_DIM + 4 * q);
        float4 vv = *(const float4*)(vbase + (size_t)r * QKV_DIM + 4 * q);
        uint32_t* kp = &sm[((r >> 3) * 16 + (q >> 1)) * 64 + (r & 7) * 8 + (q & 1)];
        kp[0] = f2tf(kk.x); kp[2] = f2tf(kk.y); kp[4] = f2tf(kk.z); kp[6] = f2tf(kk.w);
        uint32_t* vp = &sm[8192 + ((q >> 1) * 8 + (r >> 3)) * 64 + (16 * (q & 1) + (r & 3)) * 2 + ((r >> 2) & 1)];
        vp[0] = f2tf(vv.x); vp[8] = f2tf(vv.y); vp[16] = f2tf(vv.z); vp[24] = f2tf(vv.w);
    }

    float m0 = -1e30f, m1 = -1e30f, l0 = 0.f, l1 = 0.f;
    float O[16][4];
#pragma unroll
    for (int nt = 0; nt < 16; nt++)
#pragma unroll
        for (int e = 0; e < 4; e++) O[nt][e] = 0.f;

    const float scale = 0.08838834764831845f;  // 1/sqrt(128)
    int g = lane >> 2;
    int row0 = q0 + w * 16 + g;
    int ntiles = 2 * bqt + 2;

    for (int kt = 0; kt < ntiles; kt++) {
        int buf = kt & 1;
        const uint32_t* Ks = sm + buf * 16384;
        const uint32_t* Vs = Ks + 8192;
        bool has_next = (kt + 1) < ntiles;
        int k0 = kt * FKT;
        int k0n = k0 + FKT;

        // prefetch next K tile into registers (latency hidden under S-MMAs)
        float4 Kr[8];
        if (has_next) {
#pragma unroll
            for (int i = 0; i < 8; i++) {
                int id = t + i * 256;
                int r = id >> 5, q = id & 31;
                Kr[i] = *(const float4*)(kbase + (size_t)(k0n + r) * QKV_DIM + 4 * q);
            }
        }

        __syncthreads();   // staging stores of this buf (prev iter / prologue) visible

        // ---- S = Q K^T : 16 rows x 64 cols per warp ----
        float sacc[8][4];
#pragma unroll
        for (int j = 0; j < 8; j++)
#pragma unroll
            for (int e = 0; e < 4; e++) sacc[j][e] = 0.f;

#pragma unroll
        for (int kc = 0; kc < 16; kc++) {
#pragma unroll
            for (int j = 0; j < 8; j++) {
                uint32_t bf[2];
                *(uint2*)bf = *(const uint2*)&Ks[(j * 16 + kc) * 64 + lane * 2];
                mma_tf32(sacc[j], qa[kc], bf);
            }
        }

#pragma unroll
        for (int j = 0; j < 8; j++)
#pragma unroll
            for (int e = 0; e < 4; e++) sacc[j][e] *= scale;

        if (k0 + FKT - 1 > row0) {
            int colb = k0 + 2 * (lane & 3);
#pragma unroll
            for (int j = 0; j < 8; j++) {
                int c = colb + j * 8;
                if (c > row0)     sacc[j][0] = -1e30f;
                if (c + 1 > row0) sacc[j][1] = -1e30f;
                if (c > row0 + 8)     sacc[j][2] = -1e30f;
                if (c + 1 > row0 + 8) sacc[j][3] = -1e30f;
            }
        }

        // ---- register softmax (row = quad; shfl over lane&3) ----
        float mx0 = -1e30f, mx1 = -1e30f;
#pragma unroll
        for (int j = 0; j < 8; j++) {
            mx0 = fmaxf(mx0, fmaxf(sacc[j][0], sacc[j][1]));
            mx1 = fmaxf(mx1, fmaxf(sacc[j][2], sacc[j][3]));
        }
        mx0 = fmaxf(mx0, __shfl_xor_sync(~0u, mx0, 1));
        mx0 = fmaxf(mx0, __shfl_xor_sync(~0u, mx0, 2));
        mx1 = fmaxf(mx1, __shfl_xor_sync(~0u, mx1, 1));
        mx1 = fmaxf(mx1, __shfl_xor_sync(~0u, mx1, 2));
        float mn0 = fmaxf(m0, mx0), mn1 = fmaxf(m1, mx1);
        float al0 = __expf(m0 - mn0), al1 = __expf(m1 - mn1);
        m0 = mn0; m1 = mn1;

        // prefetch next V tile (latency hidden under P-store + PV-MMAs)
        float4 Vr[8];
        if (has_next) {
#pragma unroll
            for (int i = 0; i < 8; i++) {
                int id = t + i * 256;
                int r = id >> 5, q = id & 31;
                Vr[i] = *(const float4*)(vbase + (size_t)(k0n + r) * QKV_DIM + 4 * q);
            }
        }

        float s0 = 0.f, s1 = 0.f;
        uint32_t* prow = &Ps[(w * 16 + g) * PSTR + 2 * (lane & 3)];
#pragma unroll
        for (int j = 0; j < 8; j++) {
            float p0 = __expf(sacc[j][0] - mn0);
            float p1 = __expf(sacc[j][1] - mn0);
            float p2 = __expf(sacc[j][2] - mn1);
            float p3 = __expf(sacc[j][3] - mn1);
            s0 += p0 + p1;
            s1 += p2 + p3;
            uint2 lohi;
            lohi.x = f2tf(p0); lohi.y = f2tf(p1);
            *(uint2*)&prow[j * 8] = lohi;
            lohi.x = f2tf(p2); lohi.y = f2tf(p3);
            *(uint2*)&prow[8 * PSTR + j * 8] = lohi;
        }
        s0 += __shfl_xor_sync(~0u, s0, 1);
        s0 += __shfl_xor_sync(~0u, s0, 2);
        s1 += __shfl_xor_sync(~0u, s1, 1);
        s1 += __shfl_xor_sync(~0u, s1, 2);
        l0 = l0 * al0 + s0;
        l1 = l1 * al1 + s1;

#pragma unroll
        for (int nt = 0; nt < 16; nt++) {
            O[nt][0] *= al0; O[nt][1] *= al0;
            O[nt][2] *= al1; O[nt][3] *= al1;
        }
        __syncwarp();   // P rows warp-private: make cross-lane stores visible

        // ---- O += P V ----
#pragma unroll
        for (int kc = 0; kc < 8; kc++) {
            uint32_t a[4];
            const uint32_t* pb = &Ps[(w * 16 + g) * PSTR + kc * 8 + (lane & 3)];
            a[0] = pb[0];
            a[2] = pb[4];
            a[1] = pb[8 * PSTR];
            a[3] = pb[8 * PSTR + 4];
#pragma unroll
            for (int nt = 0; nt < 16; nt++) {
                uint32_t bf[2];
                *(uint2*)bf = *(const uint2*)&Vs[(nt * 8 + kc) * 64 + lane * 2];
                mma_tf32(O[nt], a, bf);
            }
        }
        __syncwarp();   // PV reads of P done before next tile's P stores

        // ---- store prefetched KV into the other buffer (readers already past) ----
        if (has_next) {
            uint32_t* Kd = sm + (buf ^ 1) * 16384;
            uint32_t* Vd = Kd + 8192;
#pragma unroll
            for (int i = 0; i < 8; i++) {
                int id = t + i * 256;
                int r = id >> 5, q = id & 31;
                uint32_t* kp = &Kd[((r >> 3) * 16 + (q >> 1)) * 64 + (r & 7) * 8 + (q & 1)];
                kp[0] = f2tf(Kr[i].x); kp[2] = f2tf(Kr[i].y);
                kp[4] = f2tf(Kr[i].z); kp[6] = f2tf(Kr[i].w);
                uint32_t* vp = &Vd[((q >> 1) * 8 + (r >> 3)) * 64 + (16 * (q & 1) + (r & 3)) * 2 + ((r >> 2) & 1)];
                vp[0] = f2tf(Vr[i].x); vp[8] = f2tf(Vr[i].y);
                vp[16] = f2tf(Vr[i].z); vp[24] = f2tf(Vr[i].w);
            }
        }
    }

    // ---- epilogue ----
    float inv0 = 1.f / l0, inv1 = 1.f / l1;
    float* ob  = attn + ((size_t)(b * SEQ) + row0) * DIM + h * HD;
    float* ob8 = ob + 8 * DIM;
#pragma unroll
    for (int nt = 0; nt < 16; nt++) {
        int c = nt * 8 + 2 * (lane & 3);
        *(float2*)(ob + c)  = make_float2(O[nt][0] * inv0, O[nt][1] * inv0);
        *(float2*)(ob8 + c) = make_float2(O[nt][2] * inv1, O[nt][3] * inv1);
    }
}

// ---------------------------------------------------------------------------
extern "C" void kernel_launch(void* const* d_in, const int* in_sizes, int n_in,
                              void* d_out, int out_size) {
    (void)in_sizes; (void)n_in; (void)out_size;
    const float* x      = (const float*)d_in[0];
    const float* freqs  = (const float*)d_in[1];
    const float* norm_w = (const float*)d_in[2];
    const float* wqkv   = (const float*)d_in[3];
    const float* wo     = (const float*)d_in[4];
    float* out = (float*)d_out;

    float *xn, *qkv, *attn;
    cudaGetSymbolAddress((void**)&xn, g_xn);
    cudaGetSymbolAddress((void**)&qkv, g_qkv);
    cudaGetSymbolAddress((void**)&attn, g_attn);

    rmsnorm_kernel<<<TOK, 256>>>(x, norm_w, xn);

    cudaFuncSetAttribute(gemm_nt_tf32, cudaFuncAttributeMaxDynamicSharedMemorySize, GEMM_SMEM);
    gemm_nt_tf32<<<dim3(QKV_DIM / TBN, TOK / TBM), 256, GEMM_SMEM>>>(xn, wqkv, qkv, TOK, QKV_DIM, DIM);

    rope_kernel<<<TOK, 256>>>(qkv, freqs);

    cudaFuncSetAttribute(flash_tc, cudaFuncAttributeMaxDynamicSharedMemorySize, FLASH_SMEM);
    flash_tc<<<dim3(SEQ / FQT, NH, BATCH), 256, FLASH_SMEM>>>(qkv, attn);

    gemm_nt_tf32<<<dim3(DIM / TBN, TOK / TBM), 256, GEMM_SMEM>>>(attn, wo, out, TOK, DIM, DIM);
}

// round 7
// speedup vs baseline: 2.5259x; 2.5259x over previous
#include <cuda_runtime.h>
#include <cuda_fp16.h>
#include <math.h>
#include <stdint.h>

#define BATCH 2
#define SEQ 2048
#define DIM 2048
#define NH 16
#define NKV 4
#define HD 128
#define QKV_DIM 3072      /* (16 + 2*4) * 128 */
#define TOK (BATCH*SEQ)   /* 4096 */

// Scratch (device globals; no runtime allocation)
__device__ __half g_xn_h[(size_t)TOK * DIM];
__device__ __half g_qkv_h[(size_t)TOK * QKV_DIM];
__device__ __half g_attn_h[(size_t)TOK * DIM];
__device__ __half g_wqkv_h[(size_t)QKV_DIM * DIM];
__device__ __half g_wo_h[(size_t)DIM * (NH * HD)];

__device__ __forceinline__ void mma_f16(float* c, const uint32_t* a, const uint32_t* b) {
    asm volatile(
        "mma.sync.aligned.m16n8k16.row.col.f32.f16.f16.f32 "
        "{%0,%1,%2,%3}, {%4,%5,%6,%7}, {%8,%9}, {%0,%1,%2,%3};"
        : "+f"(c[0]), "+f"(c[1]), "+f"(c[2]), "+f"(c[3])
        : "r"(a[0]), "r"(a[1]), "r"(a[2]), "r"(a[3]), "r"(b[0]), "r"(b[1]));
}

__device__ __forceinline__ uint32_t pack_h2(float a, float b) {
    __half2 h = __floats2half2_rn(a, b);
    return *(uint32_t*)&h;
}

__device__ __forceinline__ void store2(float* C, size_t idx, float a, float b) {
    *(float2*)&C[idx] = make_float2(a, b);
}
__device__ __forceinline__ void store2(__half* C, size_t idx, float a, float b) {
    *(__half2*)&C[idx] = __floats2half2_rn(a, b);
}

// ---------------------------------------------------------------------------
// fp32 -> fp16 bulk convert
// ---------------------------------------------------------------------------
__global__ __launch_bounds__(256) void f2h_kernel(const float4* __restrict__ in,
                                                  __half2* __restrict__ out, int n4) {
    int i = blockIdx.x * blockDim.x + threadIdx.x;
    if (i < n4) {
        float4 v = in[i];
        out[2 * i]     = __floats2half2_rn(v.x, v.y);
        out[2 * i + 1] = __floats2half2_rn(v.z, v.w);
    }
}

// ---------------------------------------------------------------------------
// RMSNorm (fp32 in, fp16 out)
// ---------------------------------------------------------------------------
__global__ __launch_bounds__(256) void rmsnorm_kernel(const float* __restrict__ x,
                                                      const float* __restrict__ w,
                                                      __half* __restrict__ out) {
    int row = blockIdx.x;
    int t = threadIdx.x;
    const float4* xr = (const float4*)(x + (size_t)row * DIM);
    float4 v[2];
    float s = 0.f;
#pragma unroll
    for (int i = 0; i < 2; i++) {
        v[i] = xr[t + i * 256];
        s += v[i].x * v[i].x + v[i].y * v[i].y + v[i].z * v[i].z + v[i].w * v[i].w;
    }
    __shared__ float red[8];
#pragma unroll
    for (int o = 16; o > 0; o >>= 1) s += __shfl_xor_sync(~0u, s, o);
    if ((t & 31) == 0) red[t >> 5] = s;
    __syncthreads();
    if (t < 32) {
        float ss = (t < 8) ? red[t] : 0.f;
#pragma unroll
        for (int o = 4; o > 0; o >>= 1) ss += __shfl_xor_sync(~0u, ss, o);
        if (t == 0) red[0] = rsqrtf(ss / (float)DIM + 1e-6f);
    }
    __syncthreads();
    float rs = red[0];
    __half2* o2 = (__half2*)(out + (size_t)row * DIM);
    const float4* w4 = (const float4*)w;
#pragma unroll
    for (int i = 0; i < 2; i++) {
        float4 wv = w4[t + i * 256];
        int idx = t + i * 256;
        o2[2 * idx]     = __floats2half2_rn(v[i].x * rs * wv.x, v[i].y * rs * wv.y);
        o2[2 * idx + 1] = __floats2half2_rn(v[i].z * rs * wv.z, v[i].w * rs * wv.w);
    }
}

// ---------------------------------------------------------------------------
// FP16 tensor-core NT GEMM: C[m][n] = sum_k A[m][k]*B[n][k]. A,B half.
// Block 128x128x32, 8 warps (warp 32x64), m16n8k16, double-buffered 32KB smem,
// 2 CTAs/SM.
// ---------------------------------------------------------------------------
#define TBM 128
#define TBN 128
#define TBK 32
#define GEMM_SMEM (8192 * 4)   /* 32KB */

template <typename OutT>
__global__ __launch_bounds__(256, 2) void gemm_nt_f16(const __half* __restrict__ A,
                                                      const __half* __restrict__ B,
                                                      OutT* __restrict__ C,
                                                      int M, int N, int K) {
    extern __shared__ uint32_t sm[];
    int t = threadIdx.x;
    int lane = t & 31, w = t >> 5;
    int wr = w & 3, wc = w >> 2;
    int m0 = blockIdx.y * TBM, n0 = blockIdx.x * TBN;

    float acc[2][8][4];
#pragma unroll
    for (int i = 0; i < 2; i++)
#pragma unroll
        for (int j = 0; j < 8; j++)
#pragma unroll
            for (int e = 0; e < 4; e++) acc[i][j][e] = 0.f;

    uint4 Ar[2], Br[2];

#define G_LOAD(k0)                                                                \
    _Pragma("unroll")                                                             \
    for (int i = 0; i < 2; i++) {                                                 \
        int id = t + i * 256;                                                     \
        int r = id >> 2, q = id & 3;                                              \
        Ar[i] = *(const uint4*)(A + (size_t)(m0 + r) * K + (k0) + 8 * q);         \
        Br[i] = *(const uint4*)(B + (size_t)(n0 + r) * K + (k0) + 8 * q);         \
    }

#define G_STORE(buf)                                                              \
    _Pragma("unroll")                                                             \
    for (int i = 0; i < 2; i++) {                                                 \
        int id = t + i * 256;                                                     \
        int r = id >> 2, q = id & 3;                                              \
        int kc = q >> 1;                                                          \
        int r16 = r & 15;                                                         \
        int ja = (r16 >> 3) + (q & 1) * 2;                                        \
        const uint32_t* aw = (const uint32_t*)&Ar[i];                             \
        uint32_t* da = &sm[(buf) * 2048 + ((r >> 4) * 2 + kc) * 128 + (r16 & 7) * 16 + ja]; \
        da[0] = aw[0]; da[4] = aw[1]; da[8] = aw[2]; da[12] = aw[3];              \
        int jj = q & 1;                                                           \
        const uint32_t* bw = (const uint32_t*)&Br[i];                             \
        uint32_t* db = &sm[4096 + (buf) * 2048 + ((r >> 3) * 2 + kc) * 64 + (r & 7) * 8 + jj]; \
        db[0] = bw[0]; db[2] = bw[1]; db[4] = bw[2]; db[6] = bw[3];               \
    }

    G_LOAD(0);
    G_STORE(0);
    __syncthreads();

    int buf = 0;
    for (int k0 = 0; k0 < K; k0 += TBK) {
        bool has_next = (k0 + TBK) < K;
        if (has_next) { G_LOAD(k0 + TBK); }

#pragma unroll
        for (int kc = 0; kc < 2; kc++) {
            uint32_t af[2][4], bf[8][2];
#pragma unroll
            for (int i = 0; i < 2; i++)
                *(uint4*)af[i] = *(const uint4*)&sm[buf * 2048 + ((wr * 2 + i) * 2 + kc) * 128 + lane * 4];
#pragma unroll
            for (int j = 0; j < 8; j++)
                *(uint2*)bf[j] = *(const uint2*)&sm[4096 + buf * 2048 + ((wc * 8 + j) * 2 + kc) * 64 + lane * 2];
#pragma unroll
            for (int i = 0; i < 2; i++)
#pragma unroll
                for (int j = 0; j < 8; j++)
                    mma_f16(acc[i][j], af[i], bf[j]);
        }

        if (has_next) { G_STORE(buf ^ 1); }
        __syncthreads();
        buf ^= 1;
    }

#pragma unroll
    for (int i = 0; i < 2; i++) {
#pragma unroll
        for (int j = 0; j < 8; j++) {
            int row = m0 + (wr * 2 + i) * 16 + (lane >> 2);
            int col = n0 + (wc * 8 + j) * 8 + 2 * (lane & 3);
            store2(C, (size_t)row * N + col, acc[i][j][0], acc[i][j][1]);
            store2(C, (size_t)(row + 8) * N + col, acc[i][j][2], acc[i][j][3]);
        }
    }
}

// ---------------------------------------------------------------------------
// RoPE in-place on fp16 qkv (q and k heads). One block per token.
// ---------------------------------------------------------------------------
__global__ __launch_bounds__(256) void rope_h_kernel(__half* __restrict__ qkvh,
                                                     const float* __restrict__ freqs) {
    int tok = blockIdx.x;
    int s = tok & (SEQ - 1);
    for (int idx = threadIdx.x; idx < (NH + NKV) * (HD / 2); idx += blockDim.x) {
        int head = idx >> 6;
        int p = idx & 63;
        size_t off = (size_t)tok * QKV_DIM +
                     (head < NH ? head * HD : NH * HD + (head - NH) * HD);
        __half2* ptr = (__half2*)(qkvh + off) + p;
        float2 cs = *(const float2*)(freqs + (s * 64 + p) * 2);
        float2 v = __half22float2(*ptr);
        *ptr = __floats2half2_rn(v.x * cs.x - v.y * cs.y, v.x * cs.y + v.y * cs.x);
    }
}

// ---------------------------------------------------------------------------
// FP16 flash attention (causal, GQA), m16n8k16.
// - Q A-frags loaded once directly from gmem.
// - P stays in registers (fp16 S C-frag layout == PV A-frag layout).
// - KV double-buffered (64KB), register prefetch, XOR-swizzled staging.
// - Per-warp skip of fully-masked KV tiles.
// ---------------------------------------------------------------------------
#define FQT 128
#define FKT 64
#define FLASH_SMEM (16384 * 4)   /* 2 bufs x (K 4096 + V 4096) u32 */

// K fragment staging: block (nt,kc) holds 64 u32; elem (jj + ((8*n8+2*kp)^(2*kc)))
__device__ __forceinline__ void stage_k(uint32_t* Kd, const uint4* Kr, int t) {
#pragma unroll
    for (int i = 0; i < 4; i++) {
        int id = t + i * 256;
        int r = id >> 4, q = id & 15;   // K row r, halves 8q..8q+7
        int kc = q >> 1, jj = q & 1;
        int nt = r >> 3, n8 = r & 7;
        const uint32_t* kw = (const uint32_t*)&Kr[i];
        uint32_t* d = &Kd[(nt * 8 + kc) * 64 + jj];
#pragma unroll
        for (int p = 0; p < 4; p++)
            d[(8 * n8 + 2 * p) ^ (kc << 1)] = kw[p];
    }
}

// V fragment staging (transpose): block (nt,kc); elem (jj + ((8*n8+2*kp)^(2*nt)))
// Vr[2i], Vr[2i+1] = rows 2rp, 2rp+1, cols 8q..8q+7.
__device__ __forceinline__ void stage_v(uint32_t* Vd, const uint4* Vr, int t) {
#pragma unroll
    for (int i = 0; i < 2; i++) {
        int id = t + i * 256;
        int rp = id >> 4, q = id & 15;
        int kc = rp >> 3;
        int jj = (rp & 7) >> 2;
        int kp = rp & 3;
        const ushort* h0 = (const ushort*)&Vr[2 * i];
        const ushort* h1 = (const ushort*)&Vr[2 * i + 1];
        uint32_t* d = &Vd[(q * 4 + kc) * 64 + jj];
#pragma unroll
        for (int e = 0; e < 8; e++)
            d[(8 * e + 2 * kp) ^ (q << 1)] = ((uint32_t)h1[e] << 16) | (uint32_t)h0[e];
    }
}

__global__ __launch_bounds__(256, 1) void flash_f16(const __half* __restrict__ qkv,
                                                    __half* __restrict__ attn) {
    extern __shared__ uint32_t sm[];

    int bqt = gridDim.x - 1 - blockIdx.x;   // heavy tiles first
    int h = blockIdx.y, b = blockIdx.z;
    int kvh = h >> 2;                       // NH/NKV = 4
    int t = threadIdx.x, lane = t & 31, w = t >> 5;
    int g = lane >> 2;
    int q0 = bqt * FQT;

    const __half* qbase = qkv + (size_t)b * SEQ * QKV_DIM + h * HD;
    const __half* kbase = qkv + (size_t)b * SEQ * QKV_DIM + NH * HD + kvh * HD;
    const __half* vbase = kbase + NKV * HD;

    // ---- Q A-frags straight from gmem ----
    uint32_t qa[8][4];
    {
        const __half* qr  = qbase + (size_t)(q0 + w * 16 + g) * QKV_DIM;
        const __half* qr8 = qr + 8 * QKV_DIM;
        int p2 = 2 * (lane & 3);
#pragma unroll
        for (int kc = 0; kc < 8; kc++) {
            qa[kc][0] = *(const uint32_t*)(qr  + 16 * kc + p2);
            qa[kc][1] = *(const uint32_t*)(qr8 + 16 * kc + p2);
            qa[kc][2] = *(const uint32_t*)(qr  + 16 * kc + p2 + 8);
            qa[kc][3] = *(const uint32_t*)(qr8 + 16 * kc + p2 + 8);
        }
    }

    // ---- stage KV tile 0 into buffer 0 ----
    {
        uint4 Kr[4], Vr[4];
#pragma unroll
        for (int i = 0; i < 4; i++) {
            int id = t + i * 256;
            Kr[i] = *(const uint4*)(kbase + (size_t)(id >> 4) * QKV_DIM + 8 * (id & 15));
        }
#pragma unroll
        for (int i = 0; i < 2; i++) {
            int id = t + i * 256;
            int rp = id >> 4, q = id & 15;
            Vr[2 * i]     = *(const uint4*)(vbase + (size_t)(2 * rp) * QKV_DIM + 8 * q);
            Vr[2 * i + 1] = *(const uint4*)(vbase + (size_t)(2 * rp + 1) * QKV_DIM + 8 * q);
        }
        stage_k(sm, Kr, t);
        stage_v(sm + 4096, Vr, t);
    }

    float m0 = -1e30f, m1 = -1e30f, l0 = 0.f, l1 = 0.f;
    float O[16][4];
#pragma unroll
    for (int nt = 0; nt < 16; nt++)
#pragma unroll
        for (int e = 0; e < 4; e++) O[nt][e] = 0.f;

    const float scale = 0.08838834764831845f;  // 1/sqrt(128)
    int row0 = q0 + w * 16 + g;
    int rowmaxw = q0 + w * 16 + 15;
    int ntiles = 2 * bqt + 2;

    for (int kt = 0; kt < ntiles; kt++) {
        int buf = kt & 1;
        const uint32_t* Ks = sm + buf * 8192;
        const uint32_t* Vs = Ks + 4096;
        bool has_next = (kt + 1) < ntiles;
        int k0 = kt * FKT;
        int k0n = k0 + FKT;
        bool active = (k0 <= rowmaxw);

        // prefetch next K tile (latency hidden under S-MMAs)
        uint4 Kr[4];
        if (has_next) {
#pragma unroll
            for (int i = 0; i < 4; i++) {
                int id = t + i * 256;
                Kr[i] = *(const uint4*)(kbase + (size_t)(k0n + (id >> 4)) * QKV_DIM + 8 * (id & 15));
            }
        }

        __syncthreads();   // stores into this buf (prev iter / prologue) visible

        float al0 = 1.f, al1 = 1.f;
        uint32_t ph[8], ph2[8];

        if (active) {
            // ---- S = Q K^T ----
            float sacc[8][4];
#pragma unroll
            for (int j = 0; j < 8; j++)
#pragma unroll
                for (int e = 0; e < 4; e++) sacc[j][e] = 0.f;
#pragma unroll
            for (int kc = 0; kc < 8; kc++) {
#pragma unroll
                for (int j = 0; j < 8; j++) {
                    uint32_t bf[2];
                    *(uint2*)bf = *(const uint2*)&Ks[(j * 8 + kc) * 64 + ((lane * 2) ^ (kc << 1))];
                    mma_f16(sacc[j], qa[kc], bf);
                }
            }
#pragma unroll
            for (int j = 0; j < 8; j++)
#pragma unroll
                for (int e = 0; e < 4; e++) sacc[j][e] *= scale;

            if (k0 + FKT - 1 > row0) {
                int colb = k0 + 2 * (lane & 3);
#pragma unroll
                for (int j = 0; j < 8; j++) {
                    int c = colb + j * 8;
                    if (c > row0)         sacc[j][0] = -1e30f;
                    if (c + 1 > row0)     sacc[j][1] = -1e30f;
                    if (c > row0 + 8)     sacc[j][2] = -1e30f;
                    if (c + 1 > row0 + 8) sacc[j][3] = -1e30f;
                }
            }

            // ---- register softmax (row = quad; shfl over lane&3) ----
            float mx0 = -1e30f, mx1 = -1e30f;
#pragma unroll
            for (int j = 0; j < 8; j++) {
                mx0 = fmaxf(mx0, fmaxf(sacc[j][0], sacc[j][1]));
                mx1 = fmaxf(mx1, fmaxf(sacc[j][2], sacc[j][3]));
            }
            mx0 = fmaxf(mx0, __shfl_xor_sync(~0u, mx0, 1));
            mx0 = fmaxf(mx0, __shfl_xor_sync(~0u, mx0, 2));
            mx1 = fmaxf(mx1, __shfl_xor_sync(~0u, mx1, 1));
            mx1 = fmaxf(mx1, __shfl_xor_sync(~0u, mx1, 2));
            float mn0 = fmaxf(m0, mx0), mn1 = fmaxf(m1, mx1);
            al0 = __expf(m0 - mn0);
            al1 = __expf(m1 - mn1);
            m0 = mn0; m1 = mn1;

            float s0 = 0.f, s1 = 0.f;
#pragma unroll
            for (int j = 0; j < 8; j++) {
                float p0 = __expf(sacc[j][0] - mn0);
                float p1 = __expf(sacc[j][1] - mn0);
                float p2 = __expf(sacc[j][2] - mn1);
                float p3 = __expf(sacc[j][3] - mn1);
                s0 += p0 + p1;
                s1 += p2 + p3;
                ph[j]  = pack_h2(p0, p1);
                ph2[j] = pack_h2(p2, p3);
            }
            s0 += __shfl_xor_sync(~0u, s0, 1);
            s0 += __shfl_xor_sync(~0u, s0, 2);
            s1 += __shfl_xor_sync(~0u, s1, 1);
            s1 += __shfl_xor_sync(~0u, s1, 2);
            l0 = l0 * al0 + s0;
            l1 = l1 * al1 + s1;
        }

        // prefetch next V tile (latency hidden under PV-MMAs)
        uint4 Vr[4];
        if (has_next) {
#pragma unroll
            for (int i = 0; i < 2; i++) {
                int id = t + i * 256;
                int rp = id >> 4, q = id & 15;
                Vr[2 * i]     = *(const uint4*)(vbase + (size_t)(k0n + 2 * rp) * QKV_DIM + 8 * q);
                Vr[2 * i + 1] = *(const uint4*)(vbase + (size_t)(k0n + 2 * rp + 1) * QKV_DIM + 8 * q);
            }
        }

        if (active) {
            // rescale O
#pragma unroll
            for (int nt = 0; nt < 16; nt++) {
                O[nt][0] *= al0; O[nt][1] *= al0;
                O[nt][2] *= al1; O[nt][3] *= al1;
            }
            // ---- O += P V  (P A-frags straight from registers) ----
#pragma unroll
            for (int kc = 0; kc < 4; kc++) {
                uint32_t a[4];
                a[0] = ph[2 * kc];
                a[1] = ph2[2 * kc];
                a[2] = ph[2 * kc + 1];
                a[3] = ph2[2 * kc + 1];
#pragma unroll
                for (int nt = 0; nt < 16; nt++) {
                    uint32_t bf[2];
                    *(uint2*)bf = *(const uint2*)&Vs[(nt * 4 + kc) * 64 + ((lane * 2) ^ (nt << 1))];
                    mma_f16(O[nt], a, bf);
                }
            }
        }

        // ---- store prefetched KV into other buffer (its readers passed the sync) ----
        if (has_next) {
            uint32_t* Kd = sm + (buf ^ 1) * 8192;
            stage_k(Kd, Kr, t);
            stage_v(Kd + 4096, Vr, t);
        }
    }

    // ---- epilogue (fp16 out) ----
    float inv0 = 1.f / l0, inv1 = 1.f / l1;
    __half* ob  = attn + ((size_t)(b * SEQ) + row0) * DIM + h * HD;
    __half* ob8 = ob + 8 * DIM;
#pragma unroll
    for (int nt = 0; nt < 16; nt++) {
        int c = nt * 8 + 2 * (lane & 3);
        *(__half2*)(ob + c)  = __floats2half2_rn(O[nt][0] * inv0, O[nt][1] * inv0);
        *(__half2*)(ob8 + c) = __floats2half2_rn(O[nt][2] * inv1, O[nt][3] * inv1);
    }
}

// ---------------------------------------------------------------------------
extern "C" void kernel_launch(void* const* d_in, const int* in_sizes, int n_in,
                              void* d_out, int out_size) {
    (void)in_sizes; (void)n_in; (void)out_size;
    const float* x      = (const float*)d_in[0];
    const float* freqs  = (const float*)d_in[1];
    const float* norm_w = (const float*)d_in[2];
    const float* wqkv   = (const float*)d_in[3];
    const float* wo     = (const float*)d_in[4];
    float* out = (float*)d_out;

    __half *xn, *qkv, *attn, *wqkv_h, *wo_h;
    cudaGetSymbolAddress((void**)&xn, g_xn_h);
    cudaGetSymbolAddress((void**)&qkv, g_qkv_h);
    cudaGetSymbolAddress((void**)&attn, g_attn_h);
    cudaGetSymbolAddress((void**)&wqkv_h, g_wqkv_h);
    cudaGetSymbolAddress((void**)&wo_h, g_wo_h);

    // weight conversion (fp32 -> fp16), every call (deterministic)
    f2h_kernel<<<(QKV_DIM * DIM / 4) / 256, 256>>>((const float4*)wqkv, (__half2*)wqkv_h,
                                                   QKV_DIM * DIM / 4);
    f2h_kernel<<<(DIM * NH * HD / 4) / 256, 256>>>((const float4*)wo, (__half2*)wo_h,
                                                   DIM * NH * HD / 4);

    rmsnorm_kernel<<<TOK, 256>>>(x, norm_w, xn);

    gemm_nt_f16<__half><<<dim3(QKV_DIM / TBN, TOK / TBM), 256, GEMM_SMEM>>>(
        xn, wqkv_h, qkv, TOK, QKV_DIM, DIM);

    rope_h_kernel<<<TOK, 256>>>(qkv, freqs);

    cudaFuncSetAttribute(flash_f16, cudaFuncAttributeMaxDynamicSharedMemorySize, FLASH_SMEM);
    flash_f16<<<dim3(SEQ / FQT, NH, BATCH), 256, FLASH_SMEM>>>(qkv, attn);

    gemm_nt_f16<float><<<dim3(DIM / TBN, TOK / TBM), 256, GEMM_SMEM>>>(
        attn, wo_h, out, TOK, DIM, DIM);
}

// round 9
// speedup vs baseline: 3.7399x; 1.4806x over previous
#include <cuda_runtime.h>
#include <cuda_fp16.h>
#include <math.h>
#include <stdint.h>

#define BATCH 2
#define SEQ 2048
#define DIM 2048
#define NH 16
#define NKV 4
#define HD 128
#define QKV_DIM 3072      /* (16 + 2*4) * 128 */
#define TOK (BATCH*SEQ)   /* 4096 */

// Scratch (device globals; no runtime allocation)
__device__ __half g_xn_h[(size_t)TOK * DIM];
__device__ __half g_qkv_h[(size_t)TOK * QKV_DIM];
__device__ __half g_attn_h[(size_t)TOK * DIM];
__device__ __half g_wqkv_h[(size_t)QKV_DIM * DIM];
__device__ __half g_wo_h[(size_t)DIM * (NH * HD)];

__device__ __forceinline__ uint32_t smem_u32(const void* p) {
    uint32_t a;
    asm("{ .reg .u64 t; cvta.to.shared.u64 t, %1; cvt.u32.u64 %0, t; }" : "=r"(a) : "l"(p));
    return a;
}

__device__ __forceinline__ void mma_f16(float* c, const uint32_t* a, const uint32_t* b) {
    asm volatile(
        "mma.sync.aligned.m16n8k16.row.col.f32.f16.f16.f32 "
        "{%0,%1,%2,%3}, {%4,%5,%6,%7}, {%8,%9}, {%0,%1,%2,%3};"
        : "+f"(c[0]), "+f"(c[1]), "+f"(c[2]), "+f"(c[3])
        : "r"(a[0]), "r"(a[1]), "r"(a[2]), "r"(a[3]), "r"(b[0]), "r"(b[1]));
}

__device__ __forceinline__ void ldsm_x4(uint32_t* r, uint32_t addr) {
    asm volatile("ldmatrix.sync.aligned.m8n8.x4.shared.b16 {%0,%1,%2,%3}, [%4];"
                 : "=r"(r[0]), "=r"(r[1]), "=r"(r[2]), "=r"(r[3]) : "r"(addr));
}

__device__ __forceinline__ void cp_async16(uint32_t dst, const void* src) {
    asm volatile("cp.async.cg.shared.global [%0], [%1], 16;" :: "r"(dst), "l"(src));
}
#define CP_COMMIT() asm volatile("cp.async.commit_group;" ::: "memory")
#define CP_WAIT(n)  asm volatile("cp.async.wait_group %0;" :: "n"(n) : "memory")

__device__ __forceinline__ uint32_t pack_h2(float a, float b) {
    __half2 h = __floats2half2_rn(a, b);
    return *(uint32_t*)&h;
}

__device__ __forceinline__ void store2(float* C, size_t idx, float a, float b) {
    *(float2*)&C[idx] = make_float2(a, b);
}
__device__ __forceinline__ void store2(__half* C, size_t idx, float a, float b) {
    *(__half2*)&C[idx] = __floats2half2_rn(a, b);
}

// ---------------------------------------------------------------------------
// fp32 -> fp16 bulk convert
// ---------------------------------------------------------------------------
__global__ __launch_bounds__(256) void f2h_kernel(const float4* __restrict__ in,
                                                  __half2* __restrict__ out, int n4) {
    int i = blockIdx.x * blockDim.x + threadIdx.x;
    if (i < n4) {
        float4 v = in[i];
        out[2 * i]     = __floats2half2_rn(v.x, v.y);
        out[2 * i + 1] = __floats2half2_rn(v.z, v.w);
    }
}

// ---------------------------------------------------------------------------
// RMSNorm (fp32 in, fp16 out)
// ---------------------------------------------------------------------------
__global__ __launch_bounds__(256) void rmsnorm_kernel(const float* __restrict__ x,
                                                      const float* __restrict__ w,
                                                      __half* __restrict__ out) {
    int row = blockIdx.x;
    int t = threadIdx.x;
    const float4* xr = (const float4*)(x + (size_t)row * DIM);
    float4 v[2];
    float s = 0.f;
#pragma unroll
    for (int i = 0; i < 2; i++) {
        v[i] = xr[t + i * 256];
        s += v[i].x * v[i].x + v[i].y * v[i].y + v[i].z * v[i].z + v[i].w * v[i].w;
    }
    __shared__ float red[8];
#pragma unroll
    for (int o = 16; o > 0; o >>= 1) s += __shfl_xor_sync(~0u, s, o);
    if ((t & 31) == 0) red[t >> 5] = s;
    __syncthreads();
    if (t < 32) {
        float ss = (t < 8) ? red[t] : 0.f;
#pragma unroll
        for (int o = 4; o > 0; o >>= 1) ss += __shfl_xor_sync(~0u, ss, o);
        if (t == 0) red[0] = rsqrtf(ss / (float)DIM + 1e-6f);
    }
    __syncthreads();
    float rs = red[0];
    __half2* o2 = (__half2*)(out + (size_t)row * DIM);
    const float4* w4 = (const float4*)w;
#pragma unroll
    for (int i = 0; i < 2; i++) {
        float4 wv = w4[t + i * 256];
        int idx = t + i * 256;
        o2[2 * idx]     = __floats2half2_rn(v[i].x * rs * wv.x, v[i].y * rs * wv.y);
        o2[2 * idx + 1] = __floats2half2_rn(v[i].z * rs * wv.z, v[i].w * rs * wv.w);
    }
}

// ---------------------------------------------------------------------------
// FP16 NT GEMM, cp.async staging + ldmatrix operands.
// C[m][n] = sum_k A[m][k]*B[n][k]. Tile 128x128, TBK=64 (128B SW128 rows),
// 3-stage cp.async pipeline, 8 warps (warp tile 32x64), 2 CTAs/SM.
// smem per stage: A 16KB + B 16KB; 3 stages = 96KB.
// ---------------------------------------------------------------------------
#define GP_STAGE 32768
#define GEMM_SMEM (3 * GP_STAGE)

template <typename OutT>
__global__ __launch_bounds__(256, 2) void gemm_cp(const __half* __restrict__ A,
                                                  const __half* __restrict__ B,
                                                  OutT* __restrict__ C,
                                                  int M, int N, int K) {
    extern __shared__ char smc[];
    uint32_t sb = smem_u32(smc);
    int t = threadIdx.x, lane = t & 31, w = t >> 5;
    int wr = w & 3, wc = w >> 2;
    int m0 = blockIdx.y * 128, n0 = blockIdx.x * 128;

    float acc[2][8][4];
#pragma unroll
    for (int i = 0; i < 2; i++)
#pragma unroll
        for (int j = 0; j < 8; j++)
#pragma unroll
            for (int e = 0; e < 4; e++) acc[i][j][e] = 0.f;

    const int KCH = K >> 6;   // chunks of 64 halves

    // cp.async issue for one chunk into stage s.
    // tasks: id = t + i*256 (i<4): r = id>>3 (row 0..127), q = id&7 (16B group)
    // dest = r*128 + ((q ^ (r&7)) << 4)   (SW128)
#define GP_ISSUE(k0, s)                                                         \
    {                                                                           \
        uint32_t ab = sb + (s) * GP_STAGE;                                      \
        uint32_t bb = ab + 16384;                                               \
        _Pragma("unroll")                                                       \
        for (int i = 0; i < 4; i++) {                                           \
            int id = t + i * 256, r = id >> 3, q = id & 7;                      \
            uint32_t doff = r * 128 + ((q ^ (r & 7)) << 4);                     \
            cp_async16(ab + doff, A + (size_t)(m0 + r) * K + (k0) + q * 8);     \
            cp_async16(bb + doff, B + (size_t)(n0 + r) * K + (k0) + q * 8);     \
        }                                                                       \
        CP_COMMIT();                                                            \
    }

    GP_ISSUE(0, 0);
    if (KCH > 1) GP_ISSUE(64, 1);

    // per-lane ldmatrix address components (shared by A and B frags)
    int rsel = (lane & 7) + ((lane >> 3) & 1) * 8;  // row within 16-row group
    int hi = (lane >> 4) & 1;                       // k8 half select

    for (int c = 0; c < KCH; c++) {
        int s = c % 3;
        CP_WAIT(1);            // chunk c's group complete (<=1 outstanding)
        __syncthreads();
        if (c + 2 < KCH) GP_ISSUE((c + 2) * 64, (c + 2) % 3);

        uint32_t ab = sb + s * GP_STAGE;
        uint32_t bb = ab + 16384;

#pragma unroll
        for (int kc = 0; kc < 4; kc++) {
            int c16 = kc * 2 + hi;
            uint32_t af[2][4], bq[4][4];
#pragma unroll
            for (int i = 0; i < 2; i++) {
                int row = wr * 32 + i * 16 + rsel;
                ldsm_x4(af[i], ab + row * 128 + ((c16 ^ (row & 7)) << 4));
            }
#pragma unroll
            for (int jp = 0; jp < 4; jp++) {
                int nrow = wc * 64 + jp * 16 + rsel;
                ldsm_x4(bq[jp], bb + nrow * 128 + ((c16 ^ (nrow & 7)) << 4));
            }
#pragma unroll
            for (int i = 0; i < 2; i++) {
#pragma unroll
                for (int jp = 0; jp < 4; jp++) {
                    uint32_t b0[2] = { bq[jp][0], bq[jp][2] };  // n0-7 of pair
                    uint32_t b1[2] = { bq[jp][1], bq[jp][3] };  // n8-15 of pair
                    mma_f16(acc[i][2 * jp], af[i], b0);
                    mma_f16(acc[i][2 * jp + 1], af[i], b1);
                }
            }
        }
        __syncthreads();   // all reads of stage s done before it is refilled
    }

#pragma unroll
    for (int i = 0; i < 2; i++) {
#pragma unroll
        for (int j = 0; j < 8; j++) {
            int row = m0 + (wr * 2 + i) * 16 + (lane >> 2);
            int col = n0 + (wc * 8 + j) * 8 + 2 * (lane & 3);
            store2(C, (size_t)row * N + col, acc[i][j][0], acc[i][j][1]);
            store2(C, (size_t)(row + 8) * N + col, acc[i][j][2], acc[i][j][3]);
        }
    }
}

// ---------------------------------------------------------------------------
// RoPE in-place on fp16 qkv (q and k heads).
// ---------------------------------------------------------------------------
__global__ __launch_bounds__(256) void rope_h_kernel(__half* __restrict__ qkvh,
                                                     const float* __restrict__ freqs) {
    int tok = blockIdx.x;
    int s = tok & (SEQ - 1);
    for (int idx = threadIdx.x; idx < (NH + NKV) * (HD / 2); idx += blockDim.x) {
        int head = idx >> 6;
        int p = idx & 63;
        size_t off = (size_t)tok * QKV_DIM +
                     (head < NH ? head * HD : NH * HD + (head - NH) * HD);
        __half2* ptr = (__half2*)(qkvh + off) + p;
        float2 cs = *(const float2*)(freqs + (s * 64 + p) * 2);
        float2 v = __half22float2(*ptr);
        *ptr = __floats2half2_rn(v.x * cs.x - v.y * cs.y, v.x * cs.y + v.y * cs.x);
    }
}

// ---------------------------------------------------------------------------
// FP16 flash attention (causal, GQA), m16n8k16 — unchanged from R6 (passing).
// ---------------------------------------------------------------------------
#define FQT 128
#define FKT 64
#define FLASH_SMEM (16384 * 4)

__device__ __forceinline__ void stage_k(uint32_t* Kd, const uint4* Kr, int t) {
#pragma unroll
    for (int i = 0; i < 4; i++) {
        int id = t + i * 256;
        int r = id >> 4, q = id & 15;
        int kc = q >> 1, jj = q & 1;
        int nt = r >> 3, n8 = r & 7;
        const uint32_t* kw = (const uint32_t*)&Kr[i];
        uint32_t* d = &Kd[(nt * 8 + kc) * 64 + jj];
#pragma unroll
        for (int p = 0; p < 4; p++)
            d[(8 * n8 + 2 * p) ^ (kc << 1)] = kw[p];
    }
}

__device__ __forceinline__ void stage_v(uint32_t* Vd, const uint4* Vr, int t) {
#pragma unroll
    for (int i = 0; i < 2; i++) {
        int id = t + i * 256;
        int rp = id >> 4, q = id & 15;
        int kc = rp >> 3;
        int jj = (rp & 7) >> 2;
        int kp = rp & 3;
        const ushort* h0 = (const ushort*)&Vr[2 * i];
        const ushort* h1 = (const ushort*)&Vr[2 * i + 1];
        uint32_t* d = &Vd[(q * 4 + kc) * 64 + jj];
#pragma unroll
        for (int e = 0; e < 8; e++)
            d[(8 * e + 2 * kp) ^ (q << 1)] = ((uint32_t)h1[e] << 16) | (uint32_t)h0[e];
    }
}

__global__ __launch_bounds__(256, 1) void flash_f16(const __half* __restrict__ qkv,
                                                    __half* __restrict__ attn) {
    extern __shared__ uint32_t sm[];

    int bqt = gridDim.x - 1 - blockIdx.x;
    int h = blockIdx.y, b = blockIdx.z;
    int kvh = h >> 2;
    int t = threadIdx.x, lane = t & 31, w = t >> 5;
    int g = lane >> 2;
    int q0 = bqt * FQT;

    const __half* qbase = qkv + (size_t)b * SEQ * QKV_DIM + h * HD;
    const __half* kbase = qkv + (size_t)b * SEQ * QKV_DIM + NH * HD + kvh * HD;
    const __half* vbase = kbase + NKV * HD;

    uint32_t qa[8][4];
    {
        const __half* qr  = qbase + (size_t)(q0 + w * 16 + g) * QKV_DIM;
        const __half* qr8 = qr + 8 * QKV_DIM;
        int p2 = 2 * (lane & 3);
#pragma unroll
        for (int kc = 0; kc < 8; kc++) {
            qa[kc][0] = *(const uint32_t*)(qr  + 16 * kc + p2);
            qa[kc][1] = *(const uint32_t*)(qr8 + 16 * kc + p2);
            qa[kc][2] = *(const uint32_t*)(qr  + 16 * kc + p2 + 8);
            qa[kc][3] = *(const uint32_t*)(qr8 + 16 * kc + p2 + 8);
        }
    }

    {
        uint4 Kr[4], Vr[4];
#pragma unroll
        for (int i = 0; i < 4; i++) {
            int id = t + i * 256;
            Kr[i] = *(const uint4*)(kbase + (size_t)(id >> 4) * QKV_DIM + 8 * (id & 15));
        }
#pragma unroll
        for (int i = 0; i < 2; i++) {
            int id = t + i * 256;
            int rp = id >> 4, q = id & 15;
            Vr[2 * i]     = *(const uint4*)(vbase + (size_t)(2 * rp) * QKV_DIM + 8 * q);
            Vr[2 * i + 1] = *(const uint4*)(vbase + (size_t)(2 * rp + 1) * QKV_DIM + 8 * q);
        }
        stage_k(sm, Kr, t);
        stage_v(sm + 4096, Vr, t);
    }

    float m0 = -1e30f, m1 = -1e30f, l0 = 0.f, l1 = 0.f;
    float O[16][4];
#pragma unroll
    for (int nt = 0; nt < 16; nt++)
#pragma unroll
        for (int e = 0; e < 4; e++) O[nt][e] = 0.f;

    const float scale = 0.08838834764831845f;
    int row0 = q0 + w * 16 + g;
    int rowmaxw = q0 + w * 16 + 15;
    int ntiles = 2 * bqt + 2;

    for (int kt = 0; kt < ntiles; kt++) {
        int buf = kt & 1;
        const uint32_t* Ks = sm + buf * 8192;
        const uint32_t* Vs = Ks + 4096;
        bool has_next = (kt + 1) < ntiles;
        int k0 = kt * FKT;
        int k0n = k0 + FKT;
        bool active = (k0 <= rowmaxw);

        uint4 Kr[4];
        if (has_next) {
#pragma unroll
            for (int i = 0; i < 4; i++) {
                int id = t + i * 256;
                Kr[i] = *(const uint4*)(kbase + (size_t)(k0n + (id >> 4)) * QKV_DIM + 8 * (id & 15));
            }
        }

        __syncthreads();

        float al0 = 1.f, al1 = 1.f;
        uint32_t ph[8], ph2[8];

        if (active) {
            float sacc[8][4];
#pragma unroll
            for (int j = 0; j < 8; j++)
#pragma unroll
                for (int e = 0; e < 4; e++) sacc[j][e] = 0.f;
#pragma unroll
            for (int kc = 0; kc < 8; kc++) {
#pragma unroll
                for (int j = 0; j < 8; j++) {
                    uint32_t bf[2];
                    *(uint2*)bf = *(const uint2*)&Ks[(j * 8 + kc) * 64 + ((lane * 2) ^ (kc << 1))];
                    mma_f16(sacc[j], qa[kc], bf);
                }
            }
#pragma unroll
            for (int j = 0; j < 8; j++)
#pragma unroll
                for (int e = 0; e < 4; e++) sacc[j][e] *= scale;

            if (k0 + FKT - 1 > row0) {
                int colb = k0 + 2 * (lane & 3);
#pragma unroll
                for (int j = 0; j < 8; j++) {
                    int c = colb + j * 8;
                    if (c > row0)         sacc[j][0] = -1e30f;
                    if (c + 1 > row0)     sacc[j][1] = -1e30f;
                    if (c > row0 + 8)     sacc[j][2] = -1e30f;
                    if (c + 1 > row0 + 8) sacc[j][3] = -1e30f;
                }
            }

            float mx0 = -1e30f, mx1 = -1e30f;
#pragma unroll
            for (int j = 0; j < 8; j++) {
                mx0 = fmaxf(mx0, fmaxf(sacc[j][0], sacc[j][1]));
                mx1 = fmaxf(mx1, fmaxf(sacc[j][2], sacc[j][3]));
            }
            mx0 = fmaxf(mx0, __shfl_xor_sync(~0u, mx0, 1));
            mx0 = fmaxf(mx0, __shfl_xor_sync(~0u, mx0, 2));
            mx1 = fmaxf(mx1, __shfl_xor_sync(~0u, mx1, 1));
            mx1 = fmaxf(mx1, __shfl_xor_sync(~0u, mx1, 2));
            float mn0 = fmaxf(m0, mx0), mn1 = fmaxf(m1, mx1);
            al0 = __expf(m0 - mn0);
            al1 = __expf(m1 - mn1);
            m0 = mn0; m1 = mn1;

            float s0 = 0.f, s1 = 0.f;
#pragma unroll
            for (int j = 0; j < 8; j++) {
                float p0 = __expf(sacc[j][0] - mn0);
                float p1 = __expf(sacc[j][1] - mn0);
                float p2 = __expf(sacc[j][2] - mn1);
                float p3 = __expf(sacc[j][3] - mn1);
                s0 += p0 + p1;
                s1 += p2 + p3;
                ph[j]  = pack_h2(p0, p1);
                ph2[j] = pack_h2(p2, p3);
            }
            s0 += __shfl_xor_sync(~0u, s0, 1);
            s0 += __shfl_xor_sync(~0u, s0, 2);
            s1 += __shfl_xor_sync(~0u, s1, 1);
            s1 += __shfl_xor_sync(~0u, s1, 2);
            l0 = l0 * al0 + s0;
            l1 = l1 * al1 + s1;
        }

        uint4 Vr[4];
        if (has_next) {
#pragma unroll
            for (int i = 0; i < 2; i++) {
                int id = t + i * 256;
                int rp = id >> 4, q = id & 15;
                Vr[2 * i]     = *(const uint4*)(vbase + (size_t)(k0n + 2 * rp) * QKV_DIM + 8 * q);
                Vr[2 * i + 1] = *(const uint4*)(vbase + (size_t)(k0n + 2 * rp + 1) * QKV_DIM + 8 * q);
            }
        }

        if (active) {
#pragma unroll
            for (int nt = 0; nt < 16; nt++) {
                O[nt][0] *= al0; O[nt][1] *= al0;
                O[nt][2] *= al1; O[nt][3] *= al1;
            }
#pragma unroll
            for (int kc = 0; kc < 4; kc++) {
                uint32_t a[4];
                a[0] = ph[2 * kc];
                a[1] = ph2[2 * kc];
                a[2] = ph[2 * kc + 1];
                a[3] = ph2[2 * kc + 1];
#pragma unroll
                for (int nt = 0; nt < 16; nt++) {
                    uint32_t bf[2];
                    *(uint2*)bf = *(const uint2*)&Vs[(nt * 4 + kc) * 64 + ((lane * 2) ^ (nt << 1))];
                    mma_f16(O[nt], a, bf);
                }
            }
        }

        if (has_next) {
            uint32_t* Kd = sm + (buf ^ 1) * 8192;
            stage_k(Kd, Kr, t);
            stage_v(Kd + 4096, Vr, t);
        }
    }

    float inv0 = 1.f / l0, inv1 = 1.f / l1;
    __half* ob  = attn + ((size_t)(b * SEQ) + row0) * DIM + h * HD;
    __half* ob8 = ob + 8 * DIM;
#pragma unroll
    for (int nt = 0; nt < 16; nt++) {
        int c = nt * 8 + 2 * (lane & 3);
        *(__half2*)(ob + c)  = __floats2half2_rn(O[nt][0] * inv0, O[nt][1] * inv0);
        *(__half2*)(ob8 + c) = __floats2half2_rn(O[nt][2] * inv1, O[nt][3] * inv1);
    }
}

// ---------------------------------------------------------------------------
extern "C" void kernel_launch(void* const* d_in, const int* in_sizes, int n_in,
                              void* d_out, int out_size) {
    (void)in_sizes; (void)n_in; (void)out_size;
    const float* x      = (const float*)d_in[0];
    const float* freqs  = (const float*)d_in[1];
    const float* norm_w = (const float*)d_in[2];
    const float* wqkv   = (const float*)d_in[3];
    const float* wo     = (const float*)d_in[4];
    float* out = (float*)d_out;

    __half *xn, *qkv, *attn, *wqkv_h, *wo_h;
    cudaGetSymbolAddress((void**)&xn, g_xn_h);
    cudaGetSymbolAddress((void**)&qkv, g_qkv_h);
    cudaGetSymbolAddress((void**)&attn, g_attn_h);
    cudaGetSymbolAddress((void**)&wqkv_h, g_wqkv_h);
    cudaGetSymbolAddress((void**)&wo_h, g_wo_h);

    f2h_kernel<<<(QKV_DIM * DIM / 4) / 256, 256>>>((const float4*)wqkv, (__half2*)wqkv_h,
                                                   QKV_DIM * DIM / 4);
    f2h_kernel<<<(DIM * NH * HD / 4) / 256, 256>>>((const float4*)wo, (__half2*)wo_h,
                                                   DIM * NH * HD / 4);

    rmsnorm_kernel<<<TOK, 256>>>(x, norm_w, xn);

    cudaFuncSetAttribute(gemm_cp<__half>, cudaFuncAttributeMaxDynamicSharedMemorySize, GEMM_SMEM);
    cudaFuncSetAttribute(gemm_cp<float>, cudaFuncAttributeMaxDynamicSharedMemorySize, GEMM_SMEM);

    gemm_cp<__half><<<dim3(QKV_DIM / 128, TOK / 128), 256, GEMM_SMEM>>>(
        xn, wqkv_h, qkv, TOK, QKV_DIM, DIM);

    rope_h_kernel<<<TOK, 256>>>(qkv, freqs);

    cudaFuncSetAttribute(flash_f16, cudaFuncAttributeMaxDynamicSharedMemorySize, FLASH_SMEM);
    flash_f16<<<dim3(SEQ / FQT, NH, BATCH), 256, FLASH_SMEM>>>(qkv, attn);

    gemm_cp<float><<<dim3(DIM / 128, TOK / 128), 256, GEMM_SMEM>>>(
        attn, wo_h, out, TOK, DIM, DIM);
}

// round 13
// speedup vs baseline: 3.9290x; 1.0506x over previous
#include <cuda_runtime.h>
#include <cuda_fp16.h>
#include <math.h>
#include <stdint.h>

#define BATCH 2
#define SEQ 2048
#define DIM 2048
#define NH 16
#define NKV 4
#define HD 128
#define QKV_DIM 3072      /* (16 + 2*4) * 128 */
#define TOK (BATCH*SEQ)   /* 4096 */

// Scratch (device globals; no runtime allocation)
__device__ __half g_xn_h[(size_t)TOK * DIM];
__device__ __half g_qkv_h[(size_t)TOK * QKV_DIM];
__device__ __half g_attn_h[(size_t)TOK * DIM];
__device__ __half g_wqkv_h[(size_t)QKV_DIM * DIM];
__device__ __half g_wo_h[(size_t)DIM * (NH * HD)];

__device__ __forceinline__ uint32_t smem_u32(const void* p) {
    uint32_t a;
    asm("{ .reg .u64 t; cvta.to.shared.u64 t, %1; cvt.u32.u64 %0, t; }" : "=r"(a) : "l"(p));
    return a;
}

__device__ __forceinline__ void mma_f16(float* c, const uint32_t* a, const uint32_t* b) {
    asm volatile(
        "mma.sync.aligned.m16n8k16.row.col.f32.f16.f16.f32 "
        "{%0,%1,%2,%3}, {%4,%5,%6,%7}, {%8,%9}, {%0,%1,%2,%3};"
        : "+f"(c[0]), "+f"(c[1]), "+f"(c[2]), "+f"(c[3])
        : "r"(a[0]), "r"(a[1]), "r"(a[2]), "r"(a[3]), "r"(b[0]), "r"(b[1]));
}

__device__ __forceinline__ void ldsm_x4(uint32_t* r, uint32_t addr) {
    asm volatile("ldmatrix.sync.aligned.m8n8.x4.shared.b16 {%0,%1,%2,%3}, [%4];"
                 : "=r"(r[0]), "=r"(r[1]), "=r"(r[2]), "=r"(r[3]) : "r"(addr));
}

__device__ __forceinline__ void ldsm_x4_t(uint32_t* r, uint32_t addr) {
    asm volatile("ldmatrix.sync.aligned.m8n8.x4.trans.shared.b16 {%0,%1,%2,%3}, [%4];"
                 : "=r"(r[0]), "=r"(r[1]), "=r"(r[2]), "=r"(r[3]) : "r"(addr));
}

__device__ __forceinline__ void cp_async16(uint32_t dst, const void* src) {
    asm volatile("cp.async.cg.shared.global [%0], [%1], 16;" :: "r"(dst), "l"(src));
}
#define CP_COMMIT() asm volatile("cp.async.commit_group;" ::: "memory")
#define CP_WAIT(n)  asm volatile("cp.async.wait_group %0;" :: "n"(n) : "memory")

__device__ __forceinline__ uint32_t pack_h2(float a, float b) {
    __half2 h = __floats2half2_rn(a, b);
    return *(uint32_t*)&h;
}

__device__ __forceinline__ void store2(float* C, size_t idx, float a, float b) {
    *(float2*)&C[idx] = make_float2(a, b);
}
__device__ __forceinline__ void store2(__half* C, size_t idx, float a, float b) {
    *(__half2*)&C[idx] = __floats2half2_rn(a, b);
}

// ---------------------------------------------------------------------------
// fp32 -> fp16 bulk convert
// ---------------------------------------------------------------------------
__global__ __launch_bounds__(256) void f2h_kernel(const float4* __restrict__ in,
                                                  __half2* __restrict__ out, int n4) {
    int i = blockIdx.x * blockDim.x + threadIdx.x;
    if (i < n4) {
        float4 v = in[i];
        out[2 * i]     = __floats2half2_rn(v.x, v.y);
        out[2 * i + 1] = __floats2half2_rn(v.z, v.w);
    }
}

// ---------------------------------------------------------------------------
// RMSNorm (fp32 in, fp16 out)
// ---------------------------------------------------------------------------
__global__ __launch_bounds__(256) void rmsnorm_kernel(const float* __restrict__ x,
                                                      const float* __restrict__ w,
                                                      __half* __restrict__ out) {
    int row = blockIdx.x;
    int t = threadIdx.x;
    const float4* xr = (const float4*)(x + (size_t)row * DIM);
    float4 v[2];
    float s = 0.f;
#pragma unroll
    for (int i = 0; i < 2; i++) {
        v[i] = xr[t + i * 256];
        s += v[i].x * v[i].x + v[i].y * v[i].y + v[i].z * v[i].z + v[i].w * v[i].w;
    }
    __shared__ float red[8];
#pragma unroll
    for (int o = 16; o > 0; o >>= 1) s += __shfl_xor_sync(~0u, s, o);
    if ((t & 31) == 0) red[t >> 5] = s;
    __syncthreads();
    if (t < 32) {
        float ss = (t < 8) ? red[t] : 0.f;
#pragma unroll
        for (int o = 4; o > 0; o >>= 1) ss += __shfl_xor_sync(~0u, ss, o);
        if (t == 0) red[0] = rsqrtf(ss / (float)DIM + 1e-6f);
    }
    __syncthreads();
    float rs = red[0];
    __half2* o2 = (__half2*)(out + (size_t)row * DIM);
    const float4* w4 = (const float4*)w;
#pragma unroll
    for (int i = 0; i < 2; i++) {
        float4 wv = w4[t + i * 256];
        int idx = t + i * 256;
        o2[2 * idx]     = __floats2half2_rn(v[i].x * rs * wv.x, v[i].y * rs * wv.y);
        o2[2 * idx + 1] = __floats2half2_rn(v[i].z * rs * wv.z, v[i].w * rs * wv.w);
    }
}

// ---------------------------------------------------------------------------
// FP16 NT GEMM, cp.async staging + ldmatrix operands (verified R8).
// ---------------------------------------------------------------------------
#define GP_STAGE 32768
#define GEMM_SMEM (3 * GP_STAGE)

template <typename OutT>
__global__ __launch_bounds__(256, 2) void gemm_cp(const __half* __restrict__ A,
                                                  const __half* __restrict__ B,
                                                  OutT* __restrict__ C,
                                                  int M, int N, int K) {
    extern __shared__ char smc[];
    uint32_t sb = smem_u32(smc);
    int t = threadIdx.x, lane = t & 31, w = t >> 5;
    int wr = w & 3, wc = w >> 2;
    int m0 = blockIdx.y * 128, n0 = blockIdx.x * 128;

    float acc[2][8][4];
#pragma unroll
    for (int i = 0; i < 2; i++)
#pragma unroll
        for (int j = 0; j < 8; j++)
#pragma unroll
            for (int e = 0; e < 4; e++) acc[i][j][e] = 0.f;

    const int KCH = K >> 6;

#define GP_ISSUE(k0, s)                                                         \
    {                                                                           \
        uint32_t ab = sb + (s) * GP_STAGE;                                      \
        uint32_t bb = ab + 16384;                                               \
        _Pragma("unroll")                                                       \
        for (int i = 0; i < 4; i++) {                                           \
            int id = t + i * 256, r = id >> 3, q = id & 7;                      \
            uint32_t doff = r * 128 + ((q ^ (r & 7)) << 4);                     \
            cp_async16(ab + doff, A + (size_t)(m0 + r) * K + (k0) + q * 8);     \
            cp_async16(bb + doff, B + (size_t)(n0 + r) * K + (k0) + q * 8);     \
        }                                                                       \
        CP_COMMIT();                                                            \
    }

    GP_ISSUE(0, 0);
    if (KCH > 1) GP_ISSUE(64, 1);

    int rsel = (lane & 7) + ((lane >> 3) & 1) * 8;
    int hi = (lane >> 4) & 1;

    for (int c = 0; c < KCH; c++) {
        int s = c % 3;
        CP_WAIT(1);
        __syncthreads();
        if (c + 2 < KCH) GP_ISSUE((c + 2) * 64, (c + 2) % 3);

        uint32_t ab = sb + s * GP_STAGE;
        uint32_t bb = ab + 16384;

#pragma unroll
        for (int kc = 0; kc < 4; kc++) {
            int c16 = kc * 2 + hi;
            uint32_t af[2][4], bq[4][4];
#pragma unroll
            for (int i = 0; i < 2; i++) {
                int row = wr * 32 + i * 16 + rsel;
                ldsm_x4(af[i], ab + row * 128 + ((c16 ^ (row & 7)) << 4));
            }
#pragma unroll
            for (int jp = 0; jp < 4; jp++) {
                int nrow = wc * 64 + jp * 16 + rsel;
                ldsm_x4(bq[jp], bb + nrow * 128 + ((c16 ^ (nrow & 7)) << 4));
            }
#pragma unroll
            for (int i = 0; i < 2; i++) {
#pragma unroll
                for (int jp = 0; jp < 4; jp++) {
                    uint32_t b0[2] = { bq[jp][0], bq[jp][2] };
                    uint32_t b1[2] = { bq[jp][1], bq[jp][3] };
                    mma_f16(acc[i][2 * jp], af[i], b0);
                    mma_f16(acc[i][2 * jp + 1], af[i], b1);
                }
            }
        }
        __syncthreads();
    }

#pragma unroll
    for (int i = 0; i < 2; i++) {
#pragma unroll
        for (int j = 0; j < 8; j++) {
            int row = m0 + (wr * 2 + i) * 16 + (lane >> 2);
            int col = n0 + (wc * 8 + j) * 8 + 2 * (lane & 3);
            store2(C, (size_t)row * N + col, acc[i][j][0], acc[i][j][1]);
            store2(C, (size_t)(row + 8) * N + col, acc[i][j][2], acc[i][j][3]);
        }
    }
}

// ---------------------------------------------------------------------------
// RoPE in-place on fp16 qkv (q and k heads).
// ---------------------------------------------------------------------------
__global__ __launch_bounds__(256) void rope_h_kernel(__half* __restrict__ qkvh,
                                                     const float* __restrict__ freqs) {
    int tok = blockIdx.x;
    int s = tok & (SEQ - 1);
    for (int idx = threadIdx.x; idx < (NH + NKV) * (HD / 2); idx += blockDim.x) {
        int head = idx >> 6;
        int p = idx & 63;
        size_t off = (size_t)tok * QKV_DIM +
                     (head < NH ? head * HD : NH * HD + (head - NH) * HD);
        __half2* ptr = (__half2*)(qkvh + off) + p;
        float2 cs = *(const float2*)(freqs + (s * 64 + p) * 2);
        float2 v = __half22float2(*ptr);
        *ptr = __floats2half2_rn(v.x * cs.x - v.y * cs.y, v.x * cs.y + v.y * cs.x);
    }
}

// ---------------------------------------------------------------------------
// FP16 flash attention (causal, GQA), cp.async KV staging + ldmatrix operands.
// KV tiles row-major SW128 (64 rows x 256B), 3-stage cp.async pipeline,
// K frags via ldsm.x4 (GEMM-B pattern), V frags via ldsm.x4.trans.
// P stays in registers. One __syncthreads per KV tile.
// ---------------------------------------------------------------------------
#define FQT 128
#define FKT 64
#define FL_STAGE 32768            /* K 16KB + V 16KB */
#define FLASH_SMEM (3 * FL_STAGE) /* 96KB */

__global__ __launch_bounds__(256, 1) void flash_f16(const __half* __restrict__ qkv,
                                                    __half* __restrict__ attn) {
    extern __shared__ char smc[];
    uint32_t sb = smem_u32(smc);

    int bqt = gridDim.x - 1 - blockIdx.x;   // heavy tiles first
    int h = blockIdx.y, b = blockIdx.z;
    int kvh = h >> 2;                       // NH/NKV = 4
    int t = threadIdx.x, lane = t & 31, w = t >> 5;
    int g = lane >> 2;
    int q0 = bqt * FQT;

    const __half* qbase = qkv + (size_t)b * SEQ * QKV_DIM + h * HD;
    const __half* kbase = qkv + (size_t)b * SEQ * QKV_DIM + NH * HD + kvh * HD;
    const __half* vbase = kbase + NKV * HD;

    // ---- Q A-frags straight from gmem ----
    uint32_t qa[8][4];
    {
        const __half* qr  = qbase + (size_t)(q0 + w * 16 + g) * QKV_DIM;
        const __half* qr8 = qr + 8 * QKV_DIM;
        int p2 = 2 * (lane & 3);
#pragma unroll
        for (int kc = 0; kc < 8; kc++) {
            qa[kc][0] = *(const uint32_t*)(qr  + 16 * kc + p2);
            qa[kc][1] = *(const uint32_t*)(qr8 + 16 * kc + p2);
            qa[kc][2] = *(const uint32_t*)(qr  + 16 * kc + p2 + 8);
            qa[kc][3] = *(const uint32_t*)(qr8 + 16 * kc + p2 + 8);
        }
    }

    // row-major SW128 staging of one KV tile (64 rows x 256B each for K and V)
#define FL_ISSUE(k0, s)                                                          \
    {                                                                            \
        uint32_t kb = sb + (s) * FL_STAGE;                                       \
        uint32_t vb = kb + 16384;                                                \
        _Pragma("unroll")                                                        \
        for (int i = 0; i < 4; i++) {                                            \
            int id = t + i * 256, r = id >> 4, q = id & 15;                      \
            uint32_t doff = r * 256 + (((q & 8) | ((q ^ (r & 7)) & 7)) << 4);    \
            cp_async16(kb + doff, kbase + (size_t)((k0) + r) * QKV_DIM + q * 8); \
            cp_async16(vb + doff, vbase + (size_t)((k0) + r) * QKV_DIM + q * 8); \
        }                                                                        \
        CP_COMMIT();                                                             \
    }

    int ntiles = 2 * bqt + 2;
    FL_ISSUE(0, 0);
    if (ntiles > 1) FL_ISSUE(FKT, 1);

    float m0 = -1e30f, m1 = -1e30f, l0 = 0.f, l1 = 0.f;
    float O[16][4];
#pragma unroll
    for (int nt = 0; nt < 16; nt++)
#pragma unroll
        for (int e = 0; e < 4; e++) O[nt][e] = 0.f;

    const float scale = 0.08838834764831845f;  // 1/sqrt(128)
    int row0 = q0 + w * 16 + g;
    int rowmaxw = q0 + w * 16 + 15;
    int rsel = (lane & 7) + ((lane >> 3) & 1) * 8;
    int hi = (lane >> 4) & 1;

    for (int kt = 0; kt < ntiles; kt++) {
        int s = kt % 3;
        int k0 = kt * FKT;
        bool active = (k0 <= rowmaxw);

        CP_WAIT(1);          // tile kt's cp.async group complete
        __syncthreads();     // visible to all; stage (kt+2)%3's readers done (tile kt-1)
        if (kt + 2 < ntiles) FL_ISSUE((kt + 2) * FKT, (kt + 2) % 3);

        uint32_t Kst = sb + s * FL_STAGE;
        uint32_t Vst = Kst + 16384;

        if (active) {
            // ---- S = Q K^T ----
            float sacc[8][4];
#pragma unroll
            for (int j = 0; j < 8; j++)
#pragma unroll
                for (int e = 0; e < 4; e++) sacc[j][e] = 0.f;

#pragma unroll
            for (int kc = 0; kc < 8; kc++) {
                int c16 = kc * 2 + hi;
#pragma unroll
                for (int jp = 0; jp < 4; jp++) {
                    int nrow = jp * 16 + rsel;
                    uint32_t bq[4];
                    ldsm_x4(bq, Kst + nrow * 256 +
                                 (((c16 & 8) | ((c16 ^ (nrow & 7)) & 7)) << 4));
                    uint32_t b0[2] = { bq[0], bq[2] };
                    uint32_t b1[2] = { bq[1], bq[3] };
                    mma_f16(sacc[2 * jp], qa[kc], b0);
                    mma_f16(sacc[2 * jp + 1], qa[kc], b1);
                }
            }

#pragma unroll
            for (int j = 0; j < 8; j++)
#pragma unroll
                for (int e = 0; e < 4; e++) sacc[j][e] *= scale;

            if (k0 + FKT - 1 > row0) {
                int colb = k0 + 2 * (lane & 3);
#pragma unroll
                for (int j = 0; j < 8; j++) {
                    int c = colb + j * 8;
                    if (c > row0)         sacc[j][0] = -1e30f;
                    if (c + 1 > row0)     sacc[j][1] = -1e30f;
                    if (c > row0 + 8)     sacc[j][2] = -1e30f;
                    if (c + 1 > row0 + 8) sacc[j][3] = -1e30f;
                }
            }

            // ---- register softmax ----
            float mx0 = -1e30f, mx1 = -1e30f;
#pragma unroll
            for (int j = 0; j < 8; j++) {
                mx0 = fmaxf(mx0, fmaxf(sacc[j][0], sacc[j][1]));
                mx1 = fmaxf(mx1, fmaxf(sacc[j][2], sacc[j][3]));
            }
            mx0 = fmaxf(mx0, __shfl_xor_sync(~0u, mx0, 1));
            mx0 = fmaxf(mx0, __shfl_xor_sync(~0u, mx0, 2));
            mx1 = fmaxf(mx1, __shfl_xor_sync(~0u, mx1, 1));
            mx1 = fmaxf(mx1, __shfl_xor_sync(~0u, mx1, 2));
            float mn0 = fmaxf(m0, mx0), mn1 = fmaxf(m1, mx1);
            float al0 = __expf(m0 - mn0), al1 = __expf(m1 - mn1);
            m0 = mn0; m1 = mn1;

            float s0 = 0.f, s1 = 0.f;
            uint32_t ph[8], ph2[8];
#pragma unroll
            for (int j = 0; j < 8; j++) {
                float p0 = __expf(sacc[j][0] - mn0);
                float p1 = __expf(sacc[j][1] - mn0);
                float p2 = __expf(sacc[j][2] - mn1);
                float p3 = __expf(sacc[j][3] - mn1);
                s0 += p0 + p1;
                s1 += p2 + p3;
                ph[j]  = pack_h2(p0, p1);
                ph2[j] = pack_h2(p2, p3);
            }
            s0 += __shfl_xor_sync(~0u, s0, 1);
            s0 += __shfl_xor_sync(~0u, s0, 2);
            s1 += __shfl_xor_sync(~0u, s1, 1);
            s1 += __shfl_xor_sync(~0u, s1, 2);
            l0 = l0 * al0 + s0;
            l1 = l1 * al1 + s1;

            // ---- rescale O, then O += P V (V frags via ldsm.trans) ----
#pragma unroll
            for (int nt = 0; nt < 16; nt++) {
                O[nt][0] *= al0; O[nt][1] *= al0;
                O[nt][2] *= al1; O[nt][3] *= al1;
            }
#pragma unroll
            for (int kc = 0; kc < 4; kc++) {
                uint32_t a[4];
                a[0] = ph[2 * kc];
                a[1] = ph2[2 * kc];
                a[2] = ph[2 * kc + 1];
                a[3] = ph2[2 * kc + 1];
                int kr = kc * 16 + rsel;
#pragma unroll
                for (int np = 0; np < 8; np++) {
                    int gg = np * 2 + hi;
                    uint32_t bq[4];
                    ldsm_x4_t(bq, Vst + kr * 256 +
                                   (((gg & 8) | ((gg ^ (kr & 7)) & 7)) << 4));
                    uint32_t b0[2] = { bq[0], bq[1] };
                    uint32_t b1[2] = { bq[2], bq[3] };
                    mma_f16(O[2 * np], a, b0);
                    mma_f16(O[2 * np + 1], a, b1);
                }
            }
        }
    }

    // ---- epilogue (fp16 out) ----
    float inv0 = 1.f / l0, inv1 = 1.f / l1;
    __half* ob  = attn + ((size_t)(b * SEQ) + row0) * DIM + h * HD;
    __half* ob8 = ob + 8 * DIM;
#pragma unroll
    for (int nt = 0; nt < 16; nt++) {
        int c = nt * 8 + 2 * (lane & 3);
        *(__half2*)(ob + c)  = __floats2half2_rn(O[nt][0] * inv0, O[nt][1] * inv0);
        *(__half2*)(ob8 + c) = __floats2half2_rn(O[nt][2] * inv1, O[nt][3] * inv1);
    }
}

// ---------------------------------------------------------------------------
extern "C" void kernel_launch(void* const* d_in, const int* in_sizes, int n_in,
                              void* d_out, int out_size) {
    (void)in_sizes; (void)n_in; (void)out_size;
    const float* x      = (const float*)d_in[0];
    const float* freqs  = (const float*)d_in[1];
    const float* norm_w = (const float*)d_in[2];
    const float* wqkv   = (const float*)d_in[3];
    const float* wo     = (const float*)d_in[4];
    float* out = (float*)d_out;

    __half *xn, *qkv, *attn, *wqkv_h, *wo_h;
    cudaGetSymbolAddress((void**)&xn, g_xn_h);
    cudaGetSymbolAddress((void**)&qkv, g_qkv_h);
    cudaGetSymbolAddress((void**)&attn, g_attn_h);
    cudaGetSymbolAddress((void**)&wqkv_h, g_wqkv_h);
    cudaGetSymbolAddress((void**)&wo_h, g_wo_h);

    f2h_kernel<<<(QKV_DIM * DIM / 4) / 256, 256>>>((const float4*)wqkv, (__half2*)wqkv_h,
                                                   QKV_DIM * DIM / 4);
    f2h_kernel<<<(DIM * NH * HD / 4) / 256, 256>>>((const float4*)wo, (__half2*)wo_h,
                                                   DIM * NH * HD / 4);

    rmsnorm_kernel<<<TOK, 256>>>(x, norm_w, xn);

    cudaFuncSetAttribute(gemm_cp<__half>, cudaFuncAttributeMaxDynamicSharedMemorySize, GEMM_SMEM);
    cudaFuncSetAttribute(gemm_cp<float>, cudaFuncAttributeMaxDynamicSharedMemorySize, GEMM_SMEM);

    gemm_cp<__half><<<dim3(QKV_DIM / 128, TOK / 128), 256, GEMM_SMEM>>>(
        xn, wqkv_h, qkv, TOK, QKV_DIM, DIM);

    rope_h_kernel<<<TOK, 256>>>(qkv, freqs);

    cudaFuncSetAttribute(flash_f16, cudaFuncAttributeMaxDynamicSharedMemorySize, FLASH_SMEM);
    flash_f16<<<dim3(SEQ / FQT, NH, BATCH), 256, FLASH_SMEM>>>(qkv, attn);

    gemm_cp<float><<<dim3(DIM / 128, TOK / 128), 256, GEMM_SMEM>>>(
        attn, wo_h, out, TOK, DIM, DIM);
}

// round 17
// speedup vs baseline: 4.0065x; 1.0197x over previous
#include <cuda_runtime.h>
#include <cuda_fp16.h>
#include <math.h>
#include <stdint.h>

#define BATCH 2
#define SEQ 2048
#define DIM 2048
#define NH 16
#define NKV 4
#define HD 128
#define QKV_DIM 3072      /* (16 + 2*4) * 128 */
#define TOK (BATCH*SEQ)   /* 4096 */
#define ROPE_COLS ((NH + NKV) * HD)   /* 2560: q+k columns get RoPE */

// Scratch (device globals; no runtime allocation)
__device__ __half g_xn_h[(size_t)TOK * DIM];
__device__ __half g_qkv_h[(size_t)TOK * QKV_DIM];
__device__ __half g_attn_h[(size_t)TOK * DIM];
__device__ __half g_wqkv_h[(size_t)QKV_DIM * DIM];
__device__ __half g_wo_h[(size_t)DIM * (NH * HD)];

__device__ __forceinline__ uint32_t smem_u32(const void* p) {
    uint32_t a;
    asm("{ .reg .u64 t; cvta.to.shared.u64 t, %1; cvt.u32.u64 %0, t; }" : "=r"(a) : "l"(p));
    return a;
}

__device__ __forceinline__ void mma_f16(float* c, const uint32_t* a, const uint32_t* b) {
    asm volatile(
        "mma.sync.aligned.m16n8k16.row.col.f32.f16.f16.f32 "
        "{%0,%1,%2,%3}, {%4,%5,%6,%7}, {%8,%9}, {%0,%1,%2,%3};"
        : "+f"(c[0]), "+f"(c[1]), "+f"(c[2]), "+f"(c[3])
        : "r"(a[0]), "r"(a[1]), "r"(a[2]), "r"(a[3]), "r"(b[0]), "r"(b[1]));
}

__device__ __forceinline__ void ldsm_x4(uint32_t* r, uint32_t addr) {
    asm volatile("ldmatrix.sync.aligned.m8n8.x4.shared.b16 {%0,%1,%2,%3}, [%4];"
                 : "=r"(r[0]), "=r"(r[1]), "=r"(r[2]), "=r"(r[3]) : "r"(addr));
}

__device__ __forceinline__ void ldsm_x4_t(uint32_t* r, uint32_t addr) {
    asm volatile("ldmatrix.sync.aligned.m8n8.x4.trans.shared.b16 {%0,%1,%2,%3}, [%4];"
                 : "=r"(r[0]), "=r"(r[1]), "=r"(r[2]), "=r"(r[3]) : "r"(addr));
}

__device__ __forceinline__ void cp_async16(uint32_t dst, const void* src) {
    asm volatile("cp.async.cg.shared.global [%0], [%1], 16;" :: "r"(dst), "l"(src));
}
#define CP_COMMIT() asm volatile("cp.async.commit_group;" ::: "memory")
#define CP_WAIT(n)  asm volatile("cp.async.wait_group %0;" :: "n"(n) : "memory")

__device__ __forceinline__ uint32_t pack_h2(float a, float b) {
    __half2 h = __floats2half2_rn(a, b);
    return *(uint32_t*)&h;
}

__device__ __forceinline__ void store2(float* C, size_t idx, float a, float b) {
    *(float2*)&C[idx] = make_float2(a, b);
}
__device__ __forceinline__ void store2(__half* C, size_t idx, float a, float b) {
    *(__half2*)&C[idx] = __floats2half2_rn(a, b);
}

// ---------------------------------------------------------------------------
// fp32 -> fp16 bulk convert
// ---------------------------------------------------------------------------
__global__ __launch_bounds__(256) void f2h_kernel(const float4* __restrict__ in,
                                                  __half2* __restrict__ out, int n4) {
    int i = blockIdx.x * blockDim.x + threadIdx.x;
    if (i < n4) {
        float4 v = in[i];
        out[2 * i]     = __floats2half2_rn(v.x, v.y);
        out[2 * i + 1] = __floats2half2_rn(v.z, v.w);
    }
}

// ---------------------------------------------------------------------------
// RMSNorm (fp32 in, fp16 out)
// ---------------------------------------------------------------------------
__global__ __launch_bounds__(256) void rmsnorm_kernel(const float* __restrict__ x,
                                                      const float* __restrict__ w,
                                                      __half* __restrict__ out) {
    int row = blockIdx.x;
    int t = threadIdx.x;
    const float4* xr = (const float4*)(x + (size_t)row * DIM);
    float4 v[2];
    float s = 0.f;
#pragma unroll
    for (int i = 0; i < 2; i++) {
        v[i] = xr[t + i * 256];
        s += v[i].x * v[i].x + v[i].y * v[i].y + v[i].z * v[i].z + v[i].w * v[i].w;
    }
    __shared__ float red[8];
#pragma unroll
    for (int o = 16; o > 0; o >>= 1) s += __shfl_xor_sync(~0u, s, o);
    if ((t & 31) == 0) red[t >> 5] = s;
    __syncthreads();
    if (t < 32) {
        float ss = (t < 8) ? red[t] : 0.f;
#pragma unroll
        for (int o = 4; o > 0; o >>= 1) ss += __shfl_xor_sync(~0u, ss, o);
        if (t == 0) red[0] = rsqrtf(ss / (float)DIM + 1e-6f);
    }
    __syncthreads();
    float rs = red[0];
    __half2* o2 = (__half2*)(out + (size_t)row * DIM);
    const float4* w4 = (const float4*)w;
#pragma unroll
    for (int i = 0; i < 2; i++) {
        float4 wv = w4[t + i * 256];
        int idx = t + i * 256;
        o2[2 * idx]     = __floats2half2_rn(v[i].x * rs * wv.x, v[i].y * rs * wv.y);
        o2[2 * idx + 1] = __floats2half2_rn(v[i].z * rs * wv.z, v[i].w * rs * wv.w);
    }
}

// ---------------------------------------------------------------------------
// FP16 NT GEMM, cp.async staging + ldmatrix operands.
// ROPE: applies rotary embedding in the epilogue for cols < 2560 (QKV GEMM).
// One __syncthreads per K-chunk (3-stage pipeline makes the 2nd redundant).
// ---------------------------------------------------------------------------
#define GP_STAGE 32768
#define GEMM_SMEM (3 * GP_STAGE)

template <typename OutT, bool ROPE>
__global__ __launch_bounds__(256, 2) void gemm_cp(const __half* __restrict__ A,
                                                  const __half* __restrict__ B,
                                                  OutT* __restrict__ C,
                                                  const float* __restrict__ freqs,
                                                  int M, int N, int K) {
    extern __shared__ char smc[];
    uint32_t sb = smem_u32(smc);
    int t = threadIdx.x, lane = t & 31, w = t >> 5;
    int wr = w & 3, wc = w >> 2;
    int m0 = blockIdx.y * 128, n0 = blockIdx.x * 128;

    float acc[2][8][4];
#pragma unroll
    for (int i = 0; i < 2; i++)
#pragma unroll
        for (int j = 0; j < 8; j++)
#pragma unroll
            for (int e = 0; e < 4; e++) acc[i][j][e] = 0.f;

    const int KCH = K >> 6;

#define GP_ISSUE(k0, s)                                                         \
    {                                                                           \
        uint32_t ab = sb + (s) * GP_STAGE;                                      \
        uint32_t bb = ab + 16384;                                               \
        _Pragma("unroll")                                                       \
        for (int i = 0; i < 4; i++) {                                           \
            int id = t + i * 256, r = id >> 3, q = id & 7;                      \
            uint32_t doff = r * 128 + ((q ^ (r & 7)) << 4);                     \
            cp_async16(ab + doff, A + (size_t)(m0 + r) * K + (k0) + q * 8);     \
            cp_async16(bb + doff, B + (size_t)(n0 + r) * K + (k0) + q * 8);     \
        }                                                                       \
        CP_COMMIT();                                                            \
    }

    GP_ISSUE(0, 0);
    if (KCH > 1) GP_ISSUE(64, 1);

    int rsel = (lane & 7) + ((lane >> 3) & 1) * 8;
    int hi = (lane >> 4) & 1;

    for (int c = 0; c < KCH; c++) {
        int s = c % 3;
        CP_WAIT(1);
        __syncthreads();   // chunk c visible; also orders prior reads of stage (c+2)%3
        if (c + 2 < KCH) GP_ISSUE((c + 2) * 64, (c + 2) % 3);

        uint32_t ab = sb + s * GP_STAGE;
        uint32_t bb = ab + 16384;

#pragma unroll
        for (int kc = 0; kc < 4; kc++) {
            int c16 = kc * 2 + hi;
            uint32_t af[2][4], bq[4][4];
#pragma unroll
            for (int i = 0; i < 2; i++) {
                int row = wr * 32 + i * 16 + rsel;
                ldsm_x4(af[i], ab + row * 128 + ((c16 ^ (row & 7)) << 4));
            }
#pragma unroll
            for (int jp = 0; jp < 4; jp++) {
                int nrow = wc * 64 + jp * 16 + rsel;
                ldsm_x4(bq[jp], bb + nrow * 128 + ((c16 ^ (nrow & 7)) << 4));
            }
#pragma unroll
            for (int i = 0; i < 2; i++) {
#pragma unroll
                for (int jp = 0; jp < 4; jp++) {
                    uint32_t b0[2] = { bq[jp][0], bq[jp][2] };
                    uint32_t b1[2] = { bq[jp][1], bq[jp][3] };
                    mma_f16(acc[i][2 * jp], af[i], b0);
                    mma_f16(acc[i][2 * jp + 1], af[i], b1);
                }
            }
        }
        // no trailing barrier: stage s is not refilled until iter c+... whose
        // top barrier orders these reads
    }
    __syncthreads();   // protect smem (none read after) + ensure pipeline drain order

#pragma unroll
    for (int i = 0; i < 2; i++) {
#pragma unroll
        for (int j = 0; j < 8; j++) {
            int row = m0 + (wr * 2 + i) * 16 + (lane >> 2);
            int col = n0 + (wc * 8 + j) * 8 + 2 * (lane & 3);
            float a0 = acc[i][j][0], a1 = acc[i][j][1];
            float a2 = acc[i][j][2], a3 = acc[i][j][3];
            if (ROPE && col < ROPE_COLS) {
                int sq = row & (SEQ - 1);
                int p = (col & 127) >> 1;
                float2 cs  = *(const float2*)(freqs + (size_t)(sq * 64 + p) * 2);
                float2 cs8 = *(const float2*)(freqs + (size_t)((sq + 8) * 64 + p) * 2);
                float r0 = a0 * cs.x  - a1 * cs.y;
                float i0 = a0 * cs.y  + a1 * cs.x;
                float r8 = a2 * cs8.x - a3 * cs8.y;
                float i8 = a2 * cs8.y + a3 * cs8.x;
                a0 = r0; a1 = i0; a2 = r8; a3 = i8;
            }
            store2(C, (size_t)row * N + col, a0, a1);
            store2(C, (size_t)(row + 8) * N + col, a2, a3);
        }
    }
}

// ---------------------------------------------------------------------------
// FP16 flash attention (causal, GQA), cp.async KV staging + ldmatrix operands.
// Unchanged from R9 (passing).
// ---------------------------------------------------------------------------
#define FQT 128
#define FKT 64
#define FL_STAGE 32768
#define FLASH_SMEM (3 * FL_STAGE)

__global__ __launch_bounds__(256, 1) void flash_f16(const __half* __restrict__ qkv,
                                                    __half* __restrict__ attn) {
    extern __shared__ char smc[];
    uint32_t sb = smem_u32(smc);

    int bqt = gridDim.x - 1 - blockIdx.x;
    int h = blockIdx.y, b = blockIdx.z;
    int kvh = h >> 2;
    int t = threadIdx.x, lane = t & 31, w = t >> 5;
    int g = lane >> 2;
    int q0 = bqt * FQT;

    const __half* qbase = qkv + (size_t)b * SEQ * QKV_DIM + h * HD;
    const __half* kbase = qkv + (size_t)b * SEQ * QKV_DIM + NH * HD + kvh * HD;
    const __half* vbase = kbase + NKV * HD;

    uint32_t qa[8][4];
    {
        const __half* qr  = qbase + (size_t)(q0 + w * 16 + g) * QKV_DIM;
        const __half* qr8 = qr + 8 * QKV_DIM;
        int p2 = 2 * (lane & 3);
#pragma unroll
        for (int kc = 0; kc < 8; kc++) {
            qa[kc][0] = *(const uint32_t*)(qr  + 16 * kc + p2);
            qa[kc][1] = *(const uint32_t*)(qr8 + 16 * kc + p2);
            qa[kc][2] = *(const uint32_t*)(qr  + 16 * kc + p2 + 8);
            qa[kc][3] = *(const uint32_t*)(qr8 + 16 * kc + p2 + 8);
        }
    }

#define FL_ISSUE(k0, s)                                                          \
    {                                                                            \
        uint32_t kb = sb + (s) * FL_STAGE;                                       \
        uint32_t vb = kb + 16384;                                                \
        _Pragma("unroll")                                                        \
        for (int i = 0; i < 4; i++) {                                            \
            int id = t + i * 256, r = id >> 4, q = id & 15;                      \
            uint32_t doff = r * 256 + (((q & 8) | ((q ^ (r & 7)) & 7)) << 4);    \
            cp_async16(kb + doff, kbase + (size_t)((k0) + r) * QKV_DIM + q * 8); \
            cp_async16(vb + doff, vbase + (size_t)((k0) + r) * QKV_DIM + q * 8); \
        }                                                                        \
        CP_COMMIT();                                                             \
    }

    int ntiles = 2 * bqt + 2;
    FL_ISSUE(0, 0);
    if (ntiles > 1) FL_ISSUE(FKT, 1);

    float m0 = -1e30f, m1 = -1e30f, l0 = 0.f, l1 = 0.f;
    float O[16][4];
#pragma unroll
    for (int nt = 0; nt < 16; nt++)
#pragma unroll
        for (int e = 0; e < 4; e++) O[nt][e] = 0.f;

    const float scale = 0.08838834764831845f;
    int row0 = q0 + w * 16 + g;
    int rowmaxw = q0 + w * 16 + 15;
    int rsel = (lane & 7) + ((lane >> 3) & 1) * 8;
    int hi = (lane >> 4) & 1;

    for (int kt = 0; kt < ntiles; kt++) {
        int s = kt % 3;
        int k0 = kt * FKT;
        bool active = (k0 <= rowmaxw);

        CP_WAIT(1);
        __syncthreads();
        if (kt + 2 < ntiles) FL_ISSUE((kt + 2) * FKT, (kt + 2) % 3);

        uint32_t Kst = sb + s * FL_STAGE;
        uint32_t Vst = Kst + 16384;

        if (active) {
            float sacc[8][4];
#pragma unroll
            for (int j = 0; j < 8; j++)
#pragma unroll
                for (int e = 0; e < 4; e++) sacc[j][e] = 0.f;

#pragma unroll
            for (int kc = 0; kc < 8; kc++) {
                int c16 = kc * 2 + hi;
#pragma unroll
                for (int jp = 0; jp < 4; jp++) {
                    int nrow = jp * 16 + rsel;
                    uint32_t bq[4];
                    ldsm_x4(bq, Kst + nrow * 256 +
                                 (((c16 & 8) | ((c16 ^ (nrow & 7)) & 7)) << 4));
                    uint32_t b0[2] = { bq[0], bq[2] };
                    uint32_t b1[2] = { bq[1], bq[3] };
                    mma_f16(sacc[2 * jp], qa[kc], b0);
                    mma_f16(sacc[2 * jp + 1], qa[kc], b1);
                }
            }

#pragma unroll
            for (int j = 0; j < 8; j++)
#pragma unroll
                for (int e = 0; e < 4; e++) sacc[j][e] *= scale;

            if (k0 + FKT - 1 > row0) {
                int colb = k0 + 2 * (lane & 3);
#pragma unroll
                for (int j = 0; j < 8; j++) {
                    int c = colb + j * 8;
                    if (c > row0)         sacc[j][0] = -1e30f;
                    if (c + 1 > row0)     sacc[j][1] = -1e30f;
                    if (c > row0 + 8)     sacc[j][2] = -1e30f;
                    if (c + 1 > row0 + 8) sacc[j][3] = -1e30f;
                }
            }

            float mx0 = -1e30f, mx1 = -1e30f;
#pragma unroll
            for (int j = 0; j < 8; j++) {
                mx0 = fmaxf(mx0, fmaxf(sacc[j][0], sacc[j][1]));
                mx1 = fmaxf(mx1, fmaxf(sacc[j][2], sacc[j][3]));
            }
            mx0 = fmaxf(mx0, __shfl_xor_sync(~0u, mx0, 1));
            mx0 = fmaxf(mx0, __shfl_xor_sync(~0u, mx0, 2));
            mx1 = fmaxf(mx1, __shfl_xor_sync(~0u, mx1, 1));
            mx1 = fmaxf(mx1, __shfl_xor_sync(~0u, mx1, 2));
            float mn0 = fmaxf(m0, mx0), mn1 = fmaxf(m1, mx1);
            float al0 = __expf(m0 - mn0), al1 = __expf(m1 - mn1);
            m0 = mn0; m1 = mn1;

            float s0 = 0.f, s1 = 0.f;
            uint32_t ph[8], ph2[8];
#pragma unroll
            for (int j = 0; j < 8; j++) {
                float p0 = __expf(sacc[j][0] - mn0);
                float p1 = __expf(sacc[j][1] - mn0);
                float p2 = __expf(sacc[j][2] - mn1);
                float p3 = __expf(sacc[j][3] - mn1);
                s0 += p0 + p1;
                s1 += p2 + p3;
                ph[j]  = pack_h2(p0, p1);
                ph2[j] = pack_h2(p2, p3);
            }
            s0 += __shfl_xor_sync(~0u, s0, 1);
            s0 += __shfl_xor_sync(~0u, s0, 2);
            s1 += __shfl_xor_sync(~0u, s1, 1);
            s1 += __shfl_xor_sync(~0u, s1, 2);
            l0 = l0 * al0 + s0;
            l1 = l1 * al1 + s1;

#pragma unroll
            for (int nt = 0; nt < 16; nt++) {
                O[nt][0] *= al0; O[nt][1] *= al0;
                O[nt][2] *= al1; O[nt][3] *= al1;
            }
#pragma unroll
            for (int kc = 0; kc < 4; kc++) {
                uint32_t a[4];
                a[0] = ph[2 * kc];
                a[1] = ph2[2 * kc];
                a[2] = ph[2 * kc + 1];
                a[3] = ph2[2 * kc + 1];
                int kr = kc * 16 + rsel;
#pragma unroll
                for (int np = 0; np < 8; np++) {
                    int gg = np * 2 + hi;
                    uint32_t bq[4];
                    ldsm_x4_t(bq, Vst + kr * 256 +
                                   (((gg & 8) | ((gg ^ (kr & 7)) & 7)) << 4));
                    uint32_t b0[2] = { bq[0], bq[1] };
                    uint32_t b1[2] = { bq[2], bq[3] };
                    mma_f16(O[2 * np], a, b0);
                    mma_f16(O[2 * np + 1], a, b1);
                }
            }
        }
    }

    float inv0 = 1.f / l0, inv1 = 1.f / l1;
    __half* ob  = attn + ((size_t)(b * SEQ) + row0) * DIM + h * HD;
    __half* ob8 = ob + 8 * DIM;
#pragma unroll
    for (int nt = 0; nt < 16; nt++) {
        int c = nt * 8 + 2 * (lane & 3);
        *(__half2*)(ob + c)  = __floats2half2_rn(O[nt][0] * inv0, O[nt][1] * inv0);
        *(__half2*)(ob8 + c) = __floats2half2_rn(O[nt][2] * inv1, O[nt][3] * inv1);
    }
}

// ---------------------------------------------------------------------------
extern "C" void kernel_launch(void* const* d_in, const int* in_sizes, int n_in,
                              void* d_out, int out_size) {
    (void)in_sizes; (void)n_in; (void)out_size;
    const float* x      = (const float*)d_in[0];
    const float* freqs  = (const float*)d_in[1];
    const float* norm_w = (const float*)d_in[2];
    const float* wqkv   = (const float*)d_in[3];
    const float* wo     = (const float*)d_in[4];
    float* out = (float*)d_out;

    __half *xn, *qkv, *attn, *wqkv_h, *wo_h;
    cudaGetSymbolAddress((void**)&xn, g_xn_h);
    cudaGetSymbolAddress((void**)&qkv, g_qkv_h);
    cudaGetSymbolAddress((void**)&attn, g_attn_h);
    cudaGetSymbolAddress((void**)&wqkv_h, g_wqkv_h);
    cudaGetSymbolAddress((void**)&wo_h, g_wo_h);

    f2h_kernel<<<(QKV_DIM * DIM / 4) / 256, 256>>>((const float4*)wqkv, (__half2*)wqkv_h,
                                                   QKV_DIM * DIM / 4);
    f2h_kernel<<<(DIM * NH * HD / 4) / 256, 256>>>((const float4*)wo, (__half2*)wo_h,
                                                   DIM * NH * HD / 4);

    rmsnorm_kernel<<<TOK, 256>>>(x, norm_w, xn);

    cudaFuncSetAttribute((const void*)&gemm_cp<__half, true>,
                         cudaFuncAttributeMaxDynamicSharedMemorySize, GEMM_SMEM);
    cudaFuncSetAttribute((const void*)&gemm_cp<float, false>,
                         cudaFuncAttributeMaxDynamicSharedMemorySize, GEMM_SMEM);

    // QKV GEMM with fused RoPE epilogue
    gemm_cp<__half, true><<<dim3(QKV_DIM / 128, TOK / 128), 256, GEMM_SMEM>>>(
        xn, wqkv_h, qkv, freqs, TOK, QKV_DIM, DIM);

    cudaFuncSetAttribute(flash_f16, cudaFuncAttributeMaxDynamicSharedMemorySize, FLASH_SMEM);
    flash_f16<<<dim3(SEQ / FQT, NH, BATCH), 256, FLASH_SMEM>>>(qkv, attn);

    gemm_cp<float, false><<<dim3(DIM / 128, TOK / 128), 256, GEMM_SMEM>>>(
        attn, wo_h, out, nullptr, TOK, DIM, DIM);
}